// round 5
// baseline (speedup 1.0000x reference)
#include <cuda_runtime.h>
#include <math.h>

#define BATCH 64
#define SEQ   512
#define EMB   1024
#define HID   1024
#define G4    4096
#define OUTD  50
#define NCTA  128   // persistent recurrence grid: 64 u-tiles x 2 directions

// ---------------- static device scratch (no cudaMalloc allowed) ----------------
__device__ float g_X  [(size_t)SEQ * BATCH * EMB];   // [s][b][e]
__device__ float g_Gf [(size_t)SEQ * BATCH * G4];    // fwd gate pre-activations
__device__ float g_Gb [(size_t)SEQ * BATCH * G4];    // bwd gate pre-activations
__device__ float g_Hf0[(size_t)SEQ * BATCH * HID];   // layer0 fwd h history
__device__ float g_Hb0[(size_t)SEQ * BATCH * HID];   // layer0 bwd h history (orig time order)
__device__ float g_Hf1[(size_t)SEQ * BATCH * HID];   // layer1 fwd h history
__device__ float g_Hb1[(size_t)SEQ * BATCH * HID];   // layer1 bwd h history (orig time order)
__device__ unsigned g_bar;                           // monotonic grid-barrier ticket counter

// ---------------- software grid barrier (all NCTA CTAs co-resident) ----------------
__device__ __forceinline__ void grid_sync()
{
    __syncthreads();
    if (threadIdx.x == 0) {
        __threadfence();                                   // release: h stores visible at L2
        unsigned ticket = atomicAdd(&g_bar, 1u);
        unsigned target = (ticket & ~(unsigned)(NCTA - 1)) + NCTA;
        while ((int)(*(volatile unsigned*)&g_bar - target) < 0) { }
        __threadfence();                                   // acquire
    }
    __syncthreads();
}

// ---------------- embedding gather: x[s][b][:] = emb[src[b][s]] ----------------
__global__ void embed_kernel(const int* __restrict__ src, const float* __restrict__ emb)
{
    size_t idx = (size_t)blockIdx.x * blockDim.x + threadIdx.x; // over S*B*(E/4)
    int    e4  = (int)(idx & (EMB / 4 - 1));
    size_t sb  = idx >> 8;
    int    b   = (int)(sb & (BATCH - 1));
    int    s   = (int)(sb >> 6);
    int    tok = src[b * SEQ + s];
    float4 v = ((const float4*)(emb + (size_t)tok * EMB))[e4];
    ((float4*)(g_X + ((size_t)s * BATCH + b) * EMB))[e4] = v;
}

// ---------------- big GEMM: C[M=32768][N=4096] = A[M][1024] * W[N][1024]^T + bias ----------------
__global__ void __launch_bounds__(256, 2)
gemm_bias_kernel(int a_sel, const float* __restrict__ Wt,
                 const float* __restrict__ bias, int c_sel)
{
    const int K = 1024, N = G4;
    const float* A = (a_sel == 0) ? g_X : (a_sel == 1) ? g_Hf0 : g_Hb0;
    float*       C = c_sel ? g_Gb : g_Gf;

    __shared__ __align__(16) float As[2][8][128];
    __shared__ __align__(16) float Bs[2][8][128];

    const int tid = threadIdx.x;
    const int tx  = tid & 15;
    const int ty  = tid >> 4;
    const int lr  = tid >> 1;
    const int lc  = (tid & 1) << 2;

    const float* Ab = A  + (size_t)blockIdx.y * 128 * K;
    const float* Wb = Wt + (size_t)blockIdx.x * 128 * K;

    float acc[8][8];
#pragma unroll
    for (int i = 0; i < 8; i++)
#pragma unroll
        for (int j = 0; j < 8; j++) acc[i][j] = 0.f;

    {
        float4 av = *(const float4*)(Ab + (size_t)lr * K + lc);
        float4 wv = *(const float4*)(Wb + (size_t)lr * K + lc);
        As[0][lc+0][lr] = av.x; As[0][lc+1][lr] = av.y; As[0][lc+2][lr] = av.z; As[0][lc+3][lr] = av.w;
        Bs[0][lc+0][lr] = wv.x; Bs[0][lc+1][lr] = wv.y; Bs[0][lc+2][lr] = wv.z; Bs[0][lc+3][lr] = wv.w;
    }
    __syncthreads();

    int buf = 0;
    for (int k0 = 0; k0 < K; k0 += 8) {
        if (k0 + 8 < K) {
            float4 av = *(const float4*)(Ab + (size_t)lr * K + (k0 + 8) + lc);
            float4 wv = *(const float4*)(Wb + (size_t)lr * K + (k0 + 8) + lc);
            int nb = buf ^ 1;
            As[nb][lc+0][lr] = av.x; As[nb][lc+1][lr] = av.y; As[nb][lc+2][lr] = av.z; As[nb][lc+3][lr] = av.w;
            Bs[nb][lc+0][lr] = wv.x; Bs[nb][lc+1][lr] = wv.y; Bs[nb][lc+2][lr] = wv.z; Bs[nb][lc+3][lr] = wv.w;
        }
#pragma unroll
        for (int k = 0; k < 8; k++) {
            float4 a0 = *(const float4*)&As[buf][k][ty * 4];
            float4 a1 = *(const float4*)&As[buf][k][64 + ty * 4];
            float4 b0 = *(const float4*)&Bs[buf][k][tx * 4];
            float4 b1 = *(const float4*)&Bs[buf][k][64 + tx * 4];
            float a[8] = {a0.x, a0.y, a0.z, a0.w, a1.x, a1.y, a1.z, a1.w};
            float b[8] = {b0.x, b0.y, b0.z, b0.w, b1.x, b1.y, b1.z, b1.w};
#pragma unroll
            for (int i = 0; i < 8; i++)
#pragma unroll
                for (int j = 0; j < 8; j++) acc[i][j] += a[i] * b[j];
        }
        __syncthreads();
        buf ^= 1;
    }

    const int col0 = blockIdx.x * 128 + tx * 4;
    const int row0 = blockIdx.y * 128 + ty * 4;
    float4 bs0 = *(const float4*)(bias + col0);
    float4 bs1 = *(const float4*)(bias + col0 + 64);
#pragma unroll
    for (int i = 0; i < 8; i++) {
        int r = row0 + ((i < 4) ? i : (60 + i));
        float4 v0 = make_float4(acc[i][0] + bs0.x, acc[i][1] + bs0.y,
                                acc[i][2] + bs0.z, acc[i][3] + bs0.w);
        float4 v1 = make_float4(acc[i][4] + bs1.x, acc[i][5] + bs1.y,
                                acc[i][6] + bs1.z, acc[i][7] + bs1.w);
        *(float4*)(C + (size_t)r * N + col0)      = v0;
        *(float4*)(C + (size_t)r * N + col0 + 64) = v1;
    }
}

// ---------------- persistent bidirectional LSTM recurrence (one launch per layer) ----------------
// Grid (NCTA=128): blockIdx.x>>6 = direction, (blockIdx.x&63)*16 = u-tile.
// Loops t = 0..SEQ-1 internally; grid barrier between steps. h(t-1) read via __ldcg
// from the H history (each address written exactly once). c kept in registers.
__global__ void __launch_bounds__(256)
lstm_recur_kernel(const float* __restrict__ Whh_f, const float* __restrict__ Whh_b,
                  int out_sel)
{
    __shared__ __align__(16) float hs[32][64];   // [k][m]        h tile
    __shared__ __align__(16) float ws[32][64];   // [k][uu*4+g]   Whh tile

    const int d  = blockIdx.x >> 6;
    const int u0 = (blockIdx.x & 63) * 16;
    const float* W     = d ? Whh_b : Whh_f;
    const float* Gd    = d ? g_Gb : g_Gf;
    float*       Hbase = out_sel ? (d ? g_Hb1 : g_Hf1) : (d ? g_Hb0 : g_Hf0);

    const int tid = threadIdx.x;
    const int tm  = tid & 15;    // 4 batch rows each
    const int tn  = tid >> 4;    // one hidden unit (all 4 gates)
    const int u   = u0 + tn;

    // loader index decomposition (column-major over smem tile -> conflict-free STS,
    // and the same (m,k4) serves both hs (m = batch) and ws (m = uu*4+g))
    const int lm0 = tid & 63;
    const int lk0 = (tid >> 6) << 2;            // 0,4,8,12 ; +16 for second chunk
    const int wrow0 = ((lm0 & 3) << 10) + u0 + (lm0 >> 2);   // g*1024 + u0 + uu

    float creg[4] = {0.f, 0.f, 0.f, 0.f};

    for (int t = 0; t < SEQ; t++) {
        const int sidx = d ? (SEQ - 1 - t) : t;
        const float* G    = Gd    + (size_t)sidx * BATCH * G4;
        float*       Hout = Hbase + (size_t)sidx * BATCH * HID;

        // prefetch gate pre-activations (DRAM) before the long k-loop
        float gpre[4][4];
#pragma unroll
        for (int mi = 0; mi < 4; mi++) {
            const float* gr = G + (size_t)(tm * 4 + mi) * G4 + u;
            gpre[mi][0] = gr[0];
            gpre[mi][1] = gr[1024];
            gpre[mi][2] = gr[2048];
            gpre[mi][3] = gr[3072];
        }

        float acc[4][4];
#pragma unroll
        for (int i = 0; i < 4; i++)
#pragma unroll
            for (int j = 0; j < 4; j++) acc[i][j] = 0.f;

        if (t > 0) {
            const float* hin = Hbase + (size_t)(d ? sidx + 1 : sidx - 1) * BATCH * HID;

            float4 hv0, hv1, wv0, wv1;
            // prefetch tile 0
            hv0 = __ldcg((const float4*)(hin + (size_t)lm0 * HID + lk0));
            hv1 = __ldcg((const float4*)(hin + (size_t)lm0 * HID + lk0 + 16));
            wv0 = *(const float4*)(W + (size_t)wrow0 * HID + lk0);
            wv1 = *(const float4*)(W + (size_t)wrow0 * HID + lk0 + 16);

            for (int k0 = 0; k0 < HID; k0 += 32) {
                __syncthreads();
                // store current tile (conflict-free: lanes span 32 distinct m-banks)
                hs[lk0+0][lm0] = hv0.x; hs[lk0+1][lm0] = hv0.y; hs[lk0+2][lm0] = hv0.z; hs[lk0+3][lm0] = hv0.w;
                hs[lk0+16][lm0] = hv1.x; hs[lk0+17][lm0] = hv1.y; hs[lk0+18][lm0] = hv1.z; hs[lk0+19][lm0] = hv1.w;
                ws[lk0+0][lm0] = wv0.x; ws[lk0+1][lm0] = wv0.y; ws[lk0+2][lm0] = wv0.z; ws[lk0+3][lm0] = wv0.w;
                ws[lk0+16][lm0] = wv1.x; ws[lk0+17][lm0] = wv1.y; ws[lk0+18][lm0] = wv1.z; ws[lk0+19][lm0] = wv1.w;
                // prefetch next tile (latency hidden under compute)
                if (k0 + 32 < HID) {
                    int kn = k0 + 32;
                    hv0 = __ldcg((const float4*)(hin + (size_t)lm0 * HID + kn + lk0));
                    hv1 = __ldcg((const float4*)(hin + (size_t)lm0 * HID + kn + lk0 + 16));
                    wv0 = *(const float4*)(W + (size_t)wrow0 * HID + kn + lk0);
                    wv1 = *(const float4*)(W + (size_t)wrow0 * HID + kn + lk0 + 16);
                }
                __syncthreads();
#pragma unroll
                for (int k = 0; k < 32; k++) {
                    float4 a = *(const float4*)&hs[k][tm * 4];
                    float4 b = *(const float4*)&ws[k][tn * 4];
                    acc[0][0] += a.x * b.x; acc[0][1] += a.x * b.y; acc[0][2] += a.x * b.z; acc[0][3] += a.x * b.w;
                    acc[1][0] += a.y * b.x; acc[1][1] += a.y * b.y; acc[1][2] += a.y * b.z; acc[1][3] += a.y * b.w;
                    acc[2][0] += a.z * b.x; acc[2][1] += a.z * b.y; acc[2][2] += a.z * b.z; acc[2][3] += a.z * b.w;
                    acc[3][0] += a.w * b.x; acc[3][1] += a.w * b.y; acc[3][2] += a.w * b.z; acc[3][3] += a.w * b.w;
                }
            }
        }

#pragma unroll
        for (int mi = 0; mi < 4; mi++) {
            float gi = acc[mi][0] + gpre[mi][0];
            float gf = acc[mi][1] + gpre[mi][1];
            float gg = acc[mi][2] + gpre[mi][2];
            float go = acc[mi][3] + gpre[mi][3];
            float iv = 1.f / (1.f + expf(-gi));
            float fv = 1.f / (1.f + expf(-gf));
            float ov = 1.f / (1.f + expf(-go));
            float cn = fv * creg[mi] + iv * tanhf(gg);
            creg[mi] = cn;
            Hout[(size_t)(tm * 4 + mi) * HID + u] = ov * tanhf(cn);
        }

        grid_sync();
    }
}

// ---------------- output projection: out[b][s][o] = [Hf1|Hb1] @ Wout^T + bout ----------------
__global__ void __launch_bounds__(256)
out_kernel(const float* __restrict__ Wout, const float* __restrict__ bout,
           float* __restrict__ out)
{
    __shared__ __align__(16) float hf[4][HID];
    __shared__ __align__(16) float hb[4][HID];
    const int tid   = threadIdx.x;
    const int pair0 = blockIdx.x * 4;

    for (int i = tid; i < 2048; i += 256) {
        int p   = i >> 9;
        int rem = i & 511;
        int sb  = pair0 + p;
        int r4  = rem & 255;
        const float* src = (rem < 256 ? g_Hf1 : g_Hb1) + (size_t)sb * HID;
        float4 v = ((const float4*)src)[r4];
        if (rem < 256) ((float4*)hf[p])[r4] = v;
        else           ((float4*)hb[p])[r4] = v;
    }
    __syncthreads();

    int p = tid >> 6;
    int o = tid & 63;
    if (o < OUTD) {
        int sb = pair0 + p;
        int s = sb >> 6, b = sb & 63;
        const float4* w0  = (const float4*)(Wout + (size_t)o * 2 * HID);
        const float4* w1  = w0 + 256;
        const float4* hf4 = (const float4*)hf[p];
        const float4* hb4 = (const float4*)hb[p];
        float acc = 0.f;
#pragma unroll 4
        for (int k = 0; k < 256; k++) {
            float4 a = hf4[k]; float4 w = w0[k];
            acc += a.x*w.x + a.y*w.y + a.z*w.z + a.w*w.w;
        }
#pragma unroll 4
        for (int k = 0; k < 256; k++) {
            float4 a = hb4[k]; float4 w = w1[k];
            acc += a.x*w.x + a.y*w.y + a.z*w.z + a.w*w.w;
        }
        out[((size_t)b * SEQ + s) * OUTD + o] = acc + bout[o];
    }
}

// ---------------- launch sequence (8 graph nodes total) ----------------
extern "C" void kernel_launch(void* const* d_in, const int* in_sizes, int n_in,
                              void* d_out, int out_size)
{
    const int*   src   = (const int*)  d_in[0];
    const float* emb   = (const float*)d_in[1];
    const float* Wih_f = (const float*)d_in[2];
    const float* Whh_f = (const float*)d_in[3];
    const float* b_f   = (const float*)d_in[4];
    const float* Wih_b = (const float*)d_in[5];
    const float* Whh_b = (const float*)d_in[6];
    const float* b_b   = (const float*)d_in[7];
    const float* Wout  = (const float*)d_in[8];
    const float* bout  = (const float*)d_in[9];
    float* out = (float*)d_out;
    (void)in_sizes; (void)n_in; (void)out_size;

    embed_kernel<<<SEQ * BATCH * (EMB / 4) / 256, 256>>>(src, emb);

    dim3 ggrid(G4 / 128, (SEQ * BATCH) / 128);   // (32, 256)

    for (int l = 0; l < 2; l++) {
        size_t woff = (size_t)l * G4 * 1024;
        int a_f = (l == 0) ? 0 : 1;
        int a_b = (l == 0) ? 0 : 2;
        gemm_bias_kernel<<<ggrid, 256>>>(a_f, Wih_f + woff, b_f + l * G4, 0);
        gemm_bias_kernel<<<ggrid, 256>>>(a_b, Wih_b + woff, b_b + l * G4, 1);
        lstm_recur_kernel<<<NCTA, 256>>>(Whh_f + woff, Whh_b + woff, l);
    }

    out_kernel<<<(SEQ * BATCH) / 4, 256>>>(Wout, bout, out);
}

// round 6
// speedup vs baseline: 1.1536x; 1.1536x over previous
#include <cuda_runtime.h>
#include <cuda_bf16.h>
#include <math.h>

#define BATCH 64
#define SEQ   512
#define EMB   1024
#define HID   1024
#define G4    4096
#define OUTD  50
#define NCTA  128   // persistent recurrence grid: 64 u-tiles x 2 directions

// ---------------- static device scratch (no cudaMalloc allowed) ----------------
__device__ float g_X  [(size_t)SEQ * BATCH * EMB];   // [s][b][e]
__device__ float g_Gf [(size_t)SEQ * BATCH * G4];    // fwd gate pre-activations
__device__ float g_Gb [(size_t)SEQ * BATCH * G4];    // bwd gate pre-activations
__device__ float g_Hf0[(size_t)SEQ * BATCH * HID];
__device__ float g_Hb0[(size_t)SEQ * BATCH * HID];
__device__ float g_Hf1[(size_t)SEQ * BATCH * HID];
__device__ float g_Hb1[(size_t)SEQ * BATCH * HID];
__device__ unsigned g_bar;                           // monotonic grid-barrier ticket

// ---------------- software grid barrier (all NCTA CTAs co-resident) ----------------
__device__ __forceinline__ void grid_sync()
{
    __syncthreads();
    if (threadIdx.x == 0) {
        __threadfence();
        unsigned ticket = atomicAdd(&g_bar, 1u);
        unsigned target = (ticket & ~(unsigned)(NCTA - 1)) + NCTA;
        while ((int)(*(volatile unsigned*)&g_bar - target) < 0) { }
        __threadfence();
    }
    __syncthreads();
}

// ---------------- embedding gather ----------------
__global__ void embed_kernel(const int* __restrict__ src, const float* __restrict__ emb)
{
    size_t idx = (size_t)blockIdx.x * blockDim.x + threadIdx.x;
    int    e4  = (int)(idx & (EMB / 4 - 1));
    size_t sb  = idx >> 8;
    int    b   = (int)(sb & (BATCH - 1));
    int    s   = (int)(sb >> 6);
    int    tok = src[b * SEQ + s];
    float4 v = ((const float4*)(emb + (size_t)tok * EMB))[e4];
    ((float4*)(g_X + ((size_t)s * BATCH + b) * EMB))[e4] = v;
}

// ---------------- tensor-core GEMM helpers ----------------
__device__ __forceinline__ void ldsm4(unsigned* r, const __nv_bfloat16* p)
{
    unsigned a = (unsigned)__cvta_generic_to_shared(p);
    asm volatile("ldmatrix.sync.aligned.m8n8.x4.shared.b16 {%0,%1,%2,%3}, [%4];"
                 : "=r"(r[0]), "=r"(r[1]), "=r"(r[2]), "=r"(r[3]) : "r"(a));
}

__device__ __forceinline__ void mma16816(float* c, const unsigned* a, const unsigned* b)
{
    asm volatile("mma.sync.aligned.m16n8k16.row.col.f32.bf16.bf16.f32 "
                 "{%0,%1,%2,%3},{%4,%5,%6,%7},{%8,%9},{%0,%1,%2,%3};"
                 : "+f"(c[0]), "+f"(c[1]), "+f"(c[2]), "+f"(c[3])
                 : "r"(a[0]), "r"(a[1]), "r"(a[2]), "r"(a[3]), "r"(b[0]), "r"(b[1]));
}

// convert float4 -> hi/lo bf16 planes, store 4 bf16 (8B) to each plane
__device__ __forceinline__ void sts_hilo(__nv_bfloat16* hi, __nv_bfloat16* lo, float4 v)
{
    __nv_bfloat16 hx = __float2bfloat16(v.x), hy = __float2bfloat16(v.y);
    __nv_bfloat16 hz = __float2bfloat16(v.z), hw = __float2bfloat16(v.w);
    __nv_bfloat16 lx = __float2bfloat16(v.x - __bfloat162float(hx));
    __nv_bfloat16 ly = __float2bfloat16(v.y - __bfloat162float(hy));
    __nv_bfloat16 lz = __float2bfloat16(v.z - __bfloat162float(hz));
    __nv_bfloat16 lw = __float2bfloat16(v.w - __bfloat162float(hw));
    ((__nv_bfloat162*)hi)[0] = __halves2bfloat162(hx, hy);
    ((__nv_bfloat162*)hi)[1] = __halves2bfloat162(hz, hw);
    ((__nv_bfloat162*)lo)[0] = __halves2bfloat162(lx, ly);
    ((__nv_bfloat162*)lo)[1] = __halves2bfloat162(lz, lw);
}

// ---------------- big GEMM on tensor cores (bf16 split-3, fp32 accum) ----------------
// C[M=32768][N=4096] = A[M][1024] * W[N][1024]^T + bias
// CTA tile 128x128, 8 warps (4 in M x 2 in N), warp tile 32x64.
// K expanded 3x via (a_hi*w_hi + a_hi*w_lo + a_lo*w_hi); smem holds hi/lo planes.
#define SKP 40   // padded smem row length (80B stride -> conflict-free ldmatrix)
__global__ void __launch_bounds__(256)
gemm_bias_kernel(int a_sel, const float* __restrict__ Wt,
                 const float* __restrict__ bias, int c_sel)
{
    const float* A = (a_sel == 0) ? g_X : (a_sel == 1) ? g_Hf0 : g_Hb0;
    float*       C = c_sel ? g_Gb : g_Gf;

    __shared__ __align__(16) __nv_bfloat16 sA[2][128][SKP];  // [hi/lo][m][k]
    __shared__ __align__(16) __nv_bfloat16 sW[2][128][SKP];  // [hi/lo][n][k]

    const int tid    = threadIdx.x;
    const int lane   = tid & 31;
    const int wid    = tid >> 5;
    const int warp_m = wid & 3;           // 4 warps over M
    const int warp_n = wid >> 2;          // 2 warps over N

    const int lrow = tid >> 2;            // 0..63 (also +64)
    const int lk   = (tid & 3) << 2;      // 0,4,8,12

    const float* Ab = A  + (size_t)blockIdx.y * 128 * 1024;
    const float* Wb = Wt + (size_t)blockIdx.x * 128 * 1024;

    float acc[2][8][4];
#pragma unroll
    for (int i = 0; i < 2; i++)
#pragma unroll
        for (int j = 0; j < 8; j++)
#pragma unroll
            for (int q = 0; q < 4; q++) acc[i][j][q] = 0.f;

    // prologue prefetch (k0 = 0)
    float4 ra0 = *(const float4*)(Ab + (size_t)lrow * 1024 + lk);
    float4 ra1 = *(const float4*)(Ab + (size_t)(lrow + 64) * 1024 + lk);
    float4 rw0 = *(const float4*)(Wb + (size_t)lrow * 1024 + lk);
    float4 rw1 = *(const float4*)(Wb + (size_t)(lrow + 64) * 1024 + lk);

    // per-warp ldmatrix source pointers (fixed within the tile)
    const int amr  = warp_m * 32 + (lane & 15);         // + mt*16
    const int akc  = (lane >> 4) << 3;                  // 0 or 8
    const int wnr  = warp_n * 64 + (lane & 7) + ((lane >> 4) << 3);  // + q*16
    const int wkc  = ((lane >> 3) & 1) << 3;            // 0 or 8

    for (int k0 = 0; k0 < 1024; k0 += 16) {
        // store current tile (fp32 -> bf16 hi/lo planes)
        sts_hilo(&sA[0][lrow][lk],      &sA[1][lrow][lk],      ra0);
        sts_hilo(&sA[0][lrow + 64][lk], &sA[1][lrow + 64][lk], ra1);
        sts_hilo(&sW[0][lrow][lk],      &sW[1][lrow][lk],      rw0);
        sts_hilo(&sW[0][lrow + 64][lk], &sW[1][lrow + 64][lk], rw1);
        __syncthreads();

        // prefetch next tile into registers (latency hidden under MMAs)
        if (k0 + 16 < 1024) {
            int kn = k0 + 16;
            ra0 = *(const float4*)(Ab + (size_t)lrow * 1024 + kn + lk);
            ra1 = *(const float4*)(Ab + (size_t)(lrow + 64) * 1024 + kn + lk);
            rw0 = *(const float4*)(Wb + (size_t)lrow * 1024 + kn + lk);
            rw1 = *(const float4*)(Wb + (size_t)(lrow + 64) * 1024 + kn + lk);
        }

        // load fragments
        unsigned Ah[2][4], Al[2][4], Wh[4][4], Wl[4][4];
#pragma unroll
        for (int mt = 0; mt < 2; mt++) {
            ldsm4(Ah[mt], &sA[0][amr + mt * 16][akc]);
            ldsm4(Al[mt], &sA[1][amr + mt * 16][akc]);
        }
#pragma unroll
        for (int q = 0; q < 4; q++) {
            ldsm4(Wh[q], &sW[0][wnr + q * 16][wkc]);
            ldsm4(Wl[q], &sW[1][wnr + q * 16][wkc]);
        }

        // 48 MMAs: hi*hi + hi*lo + lo*hi
#pragma unroll
        for (int mt = 0; mt < 2; mt++)
#pragma unroll
            for (int nt = 0; nt < 8; nt++) {
                const unsigned* bh = &Wh[nt >> 1][(nt & 1) * 2];
                const unsigned* bl = &Wl[nt >> 1][(nt & 1) * 2];
                mma16816(acc[mt][nt], Ah[mt], bh);
                mma16816(acc[mt][nt], Ah[mt], bl);
                mma16816(acc[mt][nt], Al[mt], bh);
            }
        __syncthreads();
    }

    // epilogue: add bias, store fp32
    const int rbase = blockIdx.y * 128 + warp_m * 32 + (lane >> 2);
    const int cbase = blockIdx.x * 128 + warp_n * 64 + (lane & 3) * 2;
#pragma unroll
    for (int nt = 0; nt < 8; nt++) {
        int col = cbase + nt * 8;
        float b0 = bias[col], b1 = bias[col + 1];
#pragma unroll
        for (int mt = 0; mt < 2; mt++) {
            int r = rbase + mt * 16;
            float2 v0 = make_float2(acc[mt][nt][0] + b0, acc[mt][nt][1] + b1);
            float2 v1 = make_float2(acc[mt][nt][2] + b0, acc[mt][nt][3] + b1);
            *(float2*)(C + (size_t)r * G4 + col)       = v0;
            *(float2*)(C + (size_t)(r + 8) * G4 + col) = v1;
        }
    }
}

// ---------------- persistent bidirectional LSTM recurrence (unchanged, validated) ----------------
__global__ void __launch_bounds__(256)
lstm_recur_kernel(const float* __restrict__ Whh_f, const float* __restrict__ Whh_b,
                  int out_sel)
{
    __shared__ __align__(16) float hs[32][64];
    __shared__ __align__(16) float ws[32][64];

    const int d  = blockIdx.x >> 6;
    const int u0 = (blockIdx.x & 63) * 16;
    const float* W     = d ? Whh_b : Whh_f;
    const float* Gd    = d ? g_Gb : g_Gf;
    float*       Hbase = out_sel ? (d ? g_Hb1 : g_Hf1) : (d ? g_Hb0 : g_Hf0);

    const int tid = threadIdx.x;
    const int tm  = tid & 15;
    const int tn  = tid >> 4;
    const int u   = u0 + tn;

    const int lm0 = tid & 63;
    const int lk0 = (tid >> 6) << 2;
    const int wrow0 = ((lm0 & 3) << 10) + u0 + (lm0 >> 2);

    float creg[4] = {0.f, 0.f, 0.f, 0.f};

    for (int t = 0; t < SEQ; t++) {
        const int sidx = d ? (SEQ - 1 - t) : t;
        const float* G    = Gd    + (size_t)sidx * BATCH * G4;
        float*       Hout = Hbase + (size_t)sidx * BATCH * HID;

        float gpre[4][4];
#pragma unroll
        for (int mi = 0; mi < 4; mi++) {
            const float* gr = G + (size_t)(tm * 4 + mi) * G4 + u;
            gpre[mi][0] = gr[0];
            gpre[mi][1] = gr[1024];
            gpre[mi][2] = gr[2048];
            gpre[mi][3] = gr[3072];
        }

        float acc[4][4];
#pragma unroll
        for (int i = 0; i < 4; i++)
#pragma unroll
            for (int j = 0; j < 4; j++) acc[i][j] = 0.f;

        if (t > 0) {
            const float* hin = Hbase + (size_t)(d ? sidx + 1 : sidx - 1) * BATCH * HID;

            float4 hv0, hv1, wv0, wv1;
            hv0 = __ldcg((const float4*)(hin + (size_t)lm0 * HID + lk0));
            hv1 = __ldcg((const float4*)(hin + (size_t)lm0 * HID + lk0 + 16));
            wv0 = *(const float4*)(W + (size_t)wrow0 * HID + lk0);
            wv1 = *(const float4*)(W + (size_t)wrow0 * HID + lk0 + 16);

            for (int k0 = 0; k0 < HID; k0 += 32) {
                __syncthreads();
                hs[lk0+0][lm0] = hv0.x; hs[lk0+1][lm0] = hv0.y; hs[lk0+2][lm0] = hv0.z; hs[lk0+3][lm0] = hv0.w;
                hs[lk0+16][lm0] = hv1.x; hs[lk0+17][lm0] = hv1.y; hs[lk0+18][lm0] = hv1.z; hs[lk0+19][lm0] = hv1.w;
                ws[lk0+0][lm0] = wv0.x; ws[lk0+1][lm0] = wv0.y; ws[lk0+2][lm0] = wv0.z; ws[lk0+3][lm0] = wv0.w;
                ws[lk0+16][lm0] = wv1.x; ws[lk0+17][lm0] = wv1.y; ws[lk0+18][lm0] = wv1.z; ws[lk0+19][lm0] = wv1.w;
                if (k0 + 32 < HID) {
                    int kn = k0 + 32;
                    hv0 = __ldcg((const float4*)(hin + (size_t)lm0 * HID + kn + lk0));
                    hv1 = __ldcg((const float4*)(hin + (size_t)lm0 * HID + kn + lk0 + 16));
                    wv0 = *(const float4*)(W + (size_t)wrow0 * HID + kn + lk0);
                    wv1 = *(const float4*)(W + (size_t)wrow0 * HID + kn + lk0 + 16);
                }
                __syncthreads();
#pragma unroll
                for (int k = 0; k < 32; k++) {
                    float4 a = *(const float4*)&hs[k][tm * 4];
                    float4 b = *(const float4*)&ws[k][tn * 4];
                    acc[0][0] += a.x * b.x; acc[0][1] += a.x * b.y; acc[0][2] += a.x * b.z; acc[0][3] += a.x * b.w;
                    acc[1][0] += a.y * b.x; acc[1][1] += a.y * b.y; acc[1][2] += a.y * b.z; acc[1][3] += a.y * b.w;
                    acc[2][0] += a.z * b.x; acc[2][1] += a.z * b.y; acc[2][2] += a.z * b.z; acc[2][3] += a.z * b.w;
                    acc[3][0] += a.w * b.x; acc[3][1] += a.w * b.y; acc[3][2] += a.w * b.z; acc[3][3] += a.w * b.w;
                }
            }
        }

#pragma unroll
        for (int mi = 0; mi < 4; mi++) {
            float gi = acc[mi][0] + gpre[mi][0];
            float gf = acc[mi][1] + gpre[mi][1];
            float gg = acc[mi][2] + gpre[mi][2];
            float go = acc[mi][3] + gpre[mi][3];
            float iv = 1.f / (1.f + expf(-gi));
            float fv = 1.f / (1.f + expf(-gf));
            float ov = 1.f / (1.f + expf(-go));
            float cn = fv * creg[mi] + iv * tanhf(gg);
            creg[mi] = cn;
            Hout[(size_t)(tm * 4 + mi) * HID + u] = ov * tanhf(cn);
        }

        grid_sync();
    }
}

// ---------------- output projection ----------------
__global__ void __launch_bounds__(256)
out_kernel(const float* __restrict__ Wout, const float* __restrict__ bout,
           float* __restrict__ out)
{
    __shared__ __align__(16) float hf[4][HID];
    __shared__ __align__(16) float hb[4][HID];
    const int tid   = threadIdx.x;
    const int pair0 = blockIdx.x * 4;

    for (int i = tid; i < 2048; i += 256) {
        int p   = i >> 9;
        int rem = i & 511;
        int sb  = pair0 + p;
        int r4  = rem & 255;
        const float* src = (rem < 256 ? g_Hf1 : g_Hb1) + (size_t)sb * HID;
        float4 v = ((const float4*)src)[r4];
        if (rem < 256) ((float4*)hf[p])[r4] = v;
        else           ((float4*)hb[p])[r4] = v;
    }
    __syncthreads();

    int p = tid >> 6;
    int o = tid & 63;
    if (o < OUTD) {
        int sb = pair0 + p;
        int s = sb >> 6, b = sb & 63;
        const float4* w0  = (const float4*)(Wout + (size_t)o * 2 * HID);
        const float4* w1  = w0 + 256;
        const float4* hf4 = (const float4*)hf[p];
        const float4* hb4 = (const float4*)hb[p];
        float acc = 0.f;
#pragma unroll 4
        for (int k = 0; k < 256; k++) {
            float4 a = hf4[k]; float4 w = w0[k];
            acc += a.x*w.x + a.y*w.y + a.z*w.z + a.w*w.w;
        }
#pragma unroll 4
        for (int k = 0; k < 256; k++) {
            float4 a = hb4[k]; float4 w = w1[k];
            acc += a.x*w.x + a.y*w.y + a.z*w.z + a.w*w.w;
        }
        out[((size_t)b * SEQ + s) * OUTD + o] = acc + bout[o];
    }
}

// ---------------- launch sequence (8 graph nodes) ----------------
extern "C" void kernel_launch(void* const* d_in, const int* in_sizes, int n_in,
                              void* d_out, int out_size)
{
    const int*   src   = (const int*)  d_in[0];
    const float* emb   = (const float*)d_in[1];
    const float* Wih_f = (const float*)d_in[2];
    const float* Whh_f = (const float*)d_in[3];
    const float* b_f   = (const float*)d_in[4];
    const float* Wih_b = (const float*)d_in[5];
    const float* Whh_b = (const float*)d_in[6];
    const float* b_b   = (const float*)d_in[7];
    const float* Wout  = (const float*)d_in[8];
    const float* bout  = (const float*)d_in[9];
    float* out = (float*)d_out;
    (void)in_sizes; (void)n_in; (void)out_size;

    embed_kernel<<<SEQ * BATCH * (EMB / 4) / 256, 256>>>(src, emb);

    dim3 ggrid(G4 / 128, (SEQ * BATCH) / 128);   // (32, 256)

    for (int l = 0; l < 2; l++) {
        size_t woff = (size_t)l * G4 * 1024;
        int a_f = (l == 0) ? 0 : 1;
        int a_b = (l == 0) ? 0 : 2;
        gemm_bias_kernel<<<ggrid, 256>>>(a_f, Wih_f + woff, b_f + l * G4, 0);
        gemm_bias_kernel<<<ggrid, 256>>>(a_b, Wih_b + woff, b_b + l * G4, 1);
        lstm_recur_kernel<<<NCTA, 256>>>(Whh_f + woff, Whh_b + woff, l);
    }

    out_kernel<<<(SEQ * BATCH) / 4, 256>>>(Wout, bout, out);
}

// round 7
// speedup vs baseline: 1.1606x; 1.0061x over previous
#include <cuda_runtime.h>
#include <cuda_bf16.h>
#include <math.h>

#define BATCH 64
#define SEQ   512
#define EMB   1024
#define HID   1024
#define G4    4096
#define OUTD  50
#define NCTA  128   // persistent recurrence grid

// ---------------- static device scratch (no cudaMalloc allowed) ----------------
__device__ float g_X  [(size_t)SEQ * BATCH * EMB];
__device__ float g_Gf [(size_t)SEQ * BATCH * G4];
__device__ float g_Gb [(size_t)SEQ * BATCH * G4];
__device__ float g_Hf0[(size_t)SEQ * BATCH * HID];
__device__ float g_Hb0[(size_t)SEQ * BATCH * HID];
__device__ float g_Hf1[(size_t)SEQ * BATCH * HID];
__device__ float g_Hb1[(size_t)SEQ * BATCH * HID];
__device__ unsigned g_bar;

// bf16 hi/lo planes for tensor-core GEMM (pre-converted once per use)
__device__ __nv_bfloat16 g_Ahi[(size_t)SEQ * BATCH * 1024];
__device__ __nv_bfloat16 g_Alo[(size_t)SEQ * BATCH * 1024];
__device__ __nv_bfloat16 g_Whi[2][(size_t)G4 * 1024];
__device__ __nv_bfloat16 g_Wlo[2][(size_t)G4 * 1024];

// ---------------- software grid barrier ----------------
__device__ __forceinline__ void grid_sync()
{
    __syncthreads();
    if (threadIdx.x == 0) {
        __threadfence();
        unsigned ticket = atomicAdd(&g_bar, 1u);
        unsigned target = (ticket & ~(unsigned)(NCTA - 1)) + NCTA;
        while ((int)(*(volatile unsigned*)&g_bar - target) < 0) { }
        __threadfence();
    }
    __syncthreads();
}

// ---------------- embedding gather ----------------
__global__ void embed_kernel(const int* __restrict__ src, const float* __restrict__ emb)
{
    size_t idx = (size_t)blockIdx.x * blockDim.x + threadIdx.x;
    int    e4  = (int)(idx & (EMB / 4 - 1));
    size_t sb  = idx >> 8;
    int    b   = (int)(sb & (BATCH - 1));
    int    s   = (int)(sb >> 6);
    int    tok = src[b * SEQ + s];
    float4 v = ((const float4*)(emb + (size_t)tok * EMB))[e4];
    ((float4*)(g_X + ((size_t)s * BATCH + b) * EMB))[e4] = v;
}

// ---------------- fp32 -> bf16 hi/lo plane conversion ----------------
__device__ __forceinline__ void split4(float4 v, unsigned& hi, unsigned& hi2,
                                       unsigned& lo, unsigned& lo2)
{
    __nv_bfloat16 hx = __float2bfloat16(v.x), hy = __float2bfloat16(v.y);
    __nv_bfloat16 hz = __float2bfloat16(v.z), hw = __float2bfloat16(v.w);
    __nv_bfloat162 h0 = __halves2bfloat162(hx, hy), h1 = __halves2bfloat162(hz, hw);
    __nv_bfloat162 l0 = __halves2bfloat162(__float2bfloat16(v.x - __bfloat162float(hx)),
                                           __float2bfloat16(v.y - __bfloat162float(hy)));
    __nv_bfloat162 l1 = __halves2bfloat162(__float2bfloat16(v.z - __bfloat162float(hz)),
                                           __float2bfloat16(v.w - __bfloat162float(hw)));
    hi = *(unsigned*)&h0; hi2 = *(unsigned*)&h1;
    lo = *(unsigned*)&l0; lo2 = *(unsigned*)&l1;
}

__global__ void convA_kernel(int a_sel)   // 32768x1024 fp32 -> planes
{
    const float* A = (a_sel == 0) ? g_X : (a_sel == 1) ? g_Hf0 : g_Hb0;
    size_t i = (size_t)blockIdx.x * blockDim.x + threadIdx.x;   // float4 index
    float4 v = ((const float4*)A)[i];
    unsigned h0, h1, l0, l1; split4(v, h0, h1, l0, l1);
    ((uint2*)g_Ahi)[i] = make_uint2(h0, h1);
    ((uint2*)g_Alo)[i] = make_uint2(l0, l1);
}

__global__ void convW_kernel(const float* __restrict__ W, int set)  // 4096x1024
{
    size_t i = (size_t)blockIdx.x * blockDim.x + threadIdx.x;
    float4 v = ((const float4*)W)[i];
    unsigned h0, h1, l0, l1; split4(v, h0, h1, l0, l1);
    ((uint2*)g_Whi[set])[i] = make_uint2(h0, h1);
    ((uint2*)g_Wlo[set])[i] = make_uint2(l0, l1);
}

// ---------------- tensor-core GEMM helpers ----------------
__device__ __forceinline__ void ldsm4(unsigned* r, const __nv_bfloat16* p)
{
    unsigned a = (unsigned)__cvta_generic_to_shared(p);
    asm volatile("ldmatrix.sync.aligned.m8n8.x4.shared.b16 {%0,%1,%2,%3}, [%4];"
                 : "=r"(r[0]), "=r"(r[1]), "=r"(r[2]), "=r"(r[3]) : "r"(a));
}

__device__ __forceinline__ void mma16816(float* c, const unsigned* a, const unsigned* b)
{
    asm volatile("mma.sync.aligned.m16n8k16.row.col.f32.bf16.bf16.f32 "
                 "{%0,%1,%2,%3},{%4,%5,%6,%7},{%8,%9},{%0,%1,%2,%3};"
                 : "+f"(c[0]), "+f"(c[1]), "+f"(c[2]), "+f"(c[3])
                 : "r"(a[0]), "r"(a[1]), "r"(a[2]), "r"(a[3]), "r"(b[0]), "r"(b[1]));
}

__device__ __forceinline__ void cp16(void* sdst, const void* gsrc)
{
    unsigned s = (unsigned)__cvta_generic_to_shared(sdst);
    asm volatile("cp.async.cg.shared.global [%0], [%1], 16;" :: "r"(s), "l"(gsrc) : "memory");
}

// ---------------- pipelined bf16 GEMM: C[32768][4096] = A * W^T + bias ----------------
// A/W pre-split into hi/lo bf16 planes. CTA tile 128x128, k-chunk 32, 3-stage cp.async.
// smem stage: 4 planes x 128 rows x 40 bf16 (80B padded rows) = 40960B; 3 stages = 120KB.
#define SROW 40
#define STAGE_ELEMS (128 * SROW)        // per plane
#define STAGE_BYTES (4 * STAGE_ELEMS * 2)
__global__ void __launch_bounds__(256)
gemm_bias_bf16(int set, const float* __restrict__ bias, int c_sel)
{
    extern __shared__ __align__(16) __nv_bfloat16 smem[];   // 3 stages
    float* C = c_sel ? g_Gb : g_Gf;
    const __nv_bfloat16* Ahi = g_Ahi;
    const __nv_bfloat16* Alo = g_Alo;
    const __nv_bfloat16* Whi = g_Whi[set];
    const __nv_bfloat16* Wlo = g_Wlo[set];

    const int tid    = threadIdx.x;
    const int lane   = tid & 31;
    const int wid    = tid >> 5;
    const int warp_m = wid & 3;
    const int warp_n = wid >> 2;

    const size_t rowA0 = (size_t)blockIdx.y * 128;
    const size_t rowW0 = (size_t)blockIdx.x * 128;

    // loader decomposition: 2 segments per plane per thread
    const int lr0 = (tid * 2) >> 2;          // row for i=0
    const int lc0 = ((tid * 2) & 3) * 8;     // bf16 col
    const int lr1 = (tid * 2 + 1) >> 2;
    const int lc1 = ((tid * 2 + 1) & 3) * 8;

    // fragment source coordinates
    const int amr = warp_m * 32 + (lane & 15);
    const int akc = (lane >> 4) << 3;
    const int wnr = warp_n * 64 + (lane & 7) + ((lane >> 4) << 3);
    const int wkc = ((lane >> 3) & 1) << 3;

    float acc[2][8][4];
#pragma unroll
    for (int i = 0; i < 2; i++)
#pragma unroll
        for (int j = 0; j < 8; j++)
#pragma unroll
            for (int q = 0; q < 4; q++) acc[i][j][q] = 0.f;

    auto load_stage = [&](int st, int k0) {
        __nv_bfloat16* sAh = smem + (size_t)st * 4 * STAGE_ELEMS;
        __nv_bfloat16* sAl = sAh + STAGE_ELEMS;
        __nv_bfloat16* sWh = sAl + STAGE_ELEMS;
        __nv_bfloat16* sWl = sWh + STAGE_ELEMS;
        cp16(sAh + lr0 * SROW + lc0, Ahi + (rowA0 + lr0) * 1024 + k0 + lc0);
        cp16(sAh + lr1 * SROW + lc1, Ahi + (rowA0 + lr1) * 1024 + k0 + lc1);
        cp16(sAl + lr0 * SROW + lc0, Alo + (rowA0 + lr0) * 1024 + k0 + lc0);
        cp16(sAl + lr1 * SROW + lc1, Alo + (rowA0 + lr1) * 1024 + k0 + lc1);
        cp16(sWh + lr0 * SROW + lc0, Whi + (rowW0 + lr0) * 1024 + k0 + lc0);
        cp16(sWh + lr1 * SROW + lc1, Whi + (rowW0 + lr1) * 1024 + k0 + lc1);
        cp16(sWl + lr0 * SROW + lc0, Wlo + (rowW0 + lr0) * 1024 + k0 + lc0);
        cp16(sWl + lr1 * SROW + lc1, Wlo + (rowW0 + lr1) * 1024 + k0 + lc1);
        asm volatile("cp.async.commit_group;" ::: "memory");
    };

    load_stage(0, 0);
    load_stage(1, 32);

    for (int cc = 0; cc < 32; cc++) {
        if (cc < 31) { asm volatile("cp.async.wait_group 1;" ::: "memory"); }
        else         { asm volatile("cp.async.wait_group 0;" ::: "memory"); }
        __syncthreads();
        if (cc + 2 < 32) load_stage((cc + 2) % 3, (cc + 2) * 32);

        const __nv_bfloat16* sAh = smem + (size_t)(cc % 3) * 4 * STAGE_ELEMS;
        const __nv_bfloat16* sAl = sAh + STAGE_ELEMS;
        const __nv_bfloat16* sWh = sAl + STAGE_ELEMS;
        const __nv_bfloat16* sWl = sWh + STAGE_ELEMS;

#pragma unroll
        for (int kk = 0; kk < 32; kk += 16) {
            unsigned Ah[2][4], Al[2][4], Wh[4][4], Wl[4][4];
#pragma unroll
            for (int mt = 0; mt < 2; mt++) {
                ldsm4(Ah[mt], sAh + (amr + mt * 16) * SROW + akc + kk);
                ldsm4(Al[mt], sAl + (amr + mt * 16) * SROW + akc + kk);
            }
#pragma unroll
            for (int q = 0; q < 4; q++) {
                ldsm4(Wh[q], sWh + (wnr + q * 16) * SROW + wkc + kk);
                ldsm4(Wl[q], sWl + (wnr + q * 16) * SROW + wkc + kk);
            }
#pragma unroll
            for (int mt = 0; mt < 2; mt++)
#pragma unroll
                for (int nt = 0; nt < 8; nt++) {
                    const unsigned* bh = &Wh[nt >> 1][(nt & 1) * 2];
                    const unsigned* bl = &Wl[nt >> 1][(nt & 1) * 2];
                    mma16816(acc[mt][nt], Ah[mt], bh);
                    mma16816(acc[mt][nt], Ah[mt], bl);
                    mma16816(acc[mt][nt], Al[mt], bh);
                }
        }
        __syncthreads();
    }

    const int rbase = blockIdx.y * 128 + warp_m * 32 + (lane >> 2);
    const int cbase = blockIdx.x * 128 + warp_n * 64 + (lane & 3) * 2;
#pragma unroll
    for (int nt = 0; nt < 8; nt++) {
        int col = cbase + nt * 8;
        float b0 = bias[col], b1 = bias[col + 1];
#pragma unroll
        for (int mt = 0; mt < 2; mt++) {
            int r = rbase + mt * 16;
            *(float2*)(C + (size_t)r * G4 + col) =
                make_float2(acc[mt][nt][0] + b0, acc[mt][nt][1] + b1);
            *(float2*)(C + (size_t)(r + 8) * G4 + col) =
                make_float2(acc[mt][nt][2] + b0, acc[mt][nt][3] + b1);
        }
    }
}

// ---------------- persistent bidirectional LSTM recurrence (unchanged, validated) ----------------
__global__ void __launch_bounds__(256)
lstm_recur_kernel(const float* __restrict__ Whh_f, const float* __restrict__ Whh_b,
                  int out_sel)
{
    __shared__ __align__(16) float hs[32][64];
    __shared__ __align__(16) float ws[32][64];

    const int d  = blockIdx.x >> 6;
    const int u0 = (blockIdx.x & 63) * 16;
    const float* W     = d ? Whh_b : Whh_f;
    const float* Gd    = d ? g_Gb : g_Gf;
    float*       Hbase = out_sel ? (d ? g_Hb1 : g_Hf1) : (d ? g_Hb0 : g_Hf0);

    const int tid = threadIdx.x;
    const int tm  = tid & 15;
    const int tn  = tid >> 4;
    const int u   = u0 + tn;

    const int lm0 = tid & 63;
    const int lk0 = (tid >> 6) << 2;
    const int wrow0 = ((lm0 & 3) << 10) + u0 + (lm0 >> 2);

    float creg[4] = {0.f, 0.f, 0.f, 0.f};

    for (int t = 0; t < SEQ; t++) {
        const int sidx = d ? (SEQ - 1 - t) : t;
        const float* G    = Gd    + (size_t)sidx * BATCH * G4;
        float*       Hout = Hbase + (size_t)sidx * BATCH * HID;

        float gpre[4][4];
#pragma unroll
        for (int mi = 0; mi < 4; mi++) {
            const float* gr = G + (size_t)(tm * 4 + mi) * G4 + u;
            gpre[mi][0] = gr[0];
            gpre[mi][1] = gr[1024];
            gpre[mi][2] = gr[2048];
            gpre[mi][3] = gr[3072];
        }

        float acc[4][4];
#pragma unroll
        for (int i = 0; i < 4; i++)
#pragma unroll
            for (int j = 0; j < 4; j++) acc[i][j] = 0.f;

        if (t > 0) {
            const float* hin = Hbase + (size_t)(d ? sidx + 1 : sidx - 1) * BATCH * HID;

            float4 hv0, hv1, wv0, wv1;
            hv0 = __ldcg((const float4*)(hin + (size_t)lm0 * HID + lk0));
            hv1 = __ldcg((const float4*)(hin + (size_t)lm0 * HID + lk0 + 16));
            wv0 = *(const float4*)(W + (size_t)wrow0 * HID + lk0);
            wv1 = *(const float4*)(W + (size_t)wrow0 * HID + lk0 + 16);

            for (int k0 = 0; k0 < HID; k0 += 32) {
                __syncthreads();
                hs[lk0+0][lm0] = hv0.x; hs[lk0+1][lm0] = hv0.y; hs[lk0+2][lm0] = hv0.z; hs[lk0+3][lm0] = hv0.w;
                hs[lk0+16][lm0] = hv1.x; hs[lk0+17][lm0] = hv1.y; hs[lk0+18][lm0] = hv1.z; hs[lk0+19][lm0] = hv1.w;
                ws[lk0+0][lm0] = wv0.x; ws[lk0+1][lm0] = wv0.y; ws[lk0+2][lm0] = wv0.z; ws[lk0+3][lm0] = wv0.w;
                ws[lk0+16][lm0] = wv1.x; ws[lk0+17][lm0] = wv1.y; ws[lk0+18][lm0] = wv1.z; ws[lk0+19][lm0] = wv1.w;
                if (k0 + 32 < HID) {
                    int kn = k0 + 32;
                    hv0 = __ldcg((const float4*)(hin + (size_t)lm0 * HID + kn + lk0));
                    hv1 = __ldcg((const float4*)(hin + (size_t)lm0 * HID + kn + lk0 + 16));
                    wv0 = *(const float4*)(W + (size_t)wrow0 * HID + kn + lk0);
                    wv1 = *(const float4*)(W + (size_t)wrow0 * HID + kn + lk0 + 16);
                }
                __syncthreads();
#pragma unroll
                for (int k = 0; k < 32; k++) {
                    float4 a = *(const float4*)&hs[k][tm * 4];
                    float4 b = *(const float4*)&ws[k][tn * 4];
                    acc[0][0] += a.x * b.x; acc[0][1] += a.x * b.y; acc[0][2] += a.x * b.z; acc[0][3] += a.x * b.w;
                    acc[1][0] += a.y * b.x; acc[1][1] += a.y * b.y; acc[1][2] += a.y * b.z; acc[1][3] += a.y * b.w;
                    acc[2][0] += a.z * b.x; acc[2][1] += a.z * b.y; acc[2][2] += a.z * b.z; acc[2][3] += a.z * b.w;
                    acc[3][0] += a.w * b.x; acc[3][1] += a.w * b.y; acc[3][2] += a.w * b.z; acc[3][3] += a.w * b.w;
                }
            }
        }

#pragma unroll
        for (int mi = 0; mi < 4; mi++) {
            float gi = acc[mi][0] + gpre[mi][0];
            float gf = acc[mi][1] + gpre[mi][1];
            float gg = acc[mi][2] + gpre[mi][2];
            float go = acc[mi][3] + gpre[mi][3];
            float iv = 1.f / (1.f + expf(-gi));
            float fv = 1.f / (1.f + expf(-gf));
            float ov = 1.f / (1.f + expf(-go));
            float cn = fv * creg[mi] + iv * tanhf(gg);
            creg[mi] = cn;
            Hout[(size_t)(tm * 4 + mi) * HID + u] = ov * tanhf(cn);
        }

        grid_sync();
    }
}

// ---------------- output projection ----------------
__global__ void __launch_bounds__(256)
out_kernel(const float* __restrict__ Wout, const float* __restrict__ bout,
           float* __restrict__ out)
{
    __shared__ __align__(16) float hf[4][HID];
    __shared__ __align__(16) float hb[4][HID];
    const int tid   = threadIdx.x;
    const int pair0 = blockIdx.x * 4;

    for (int i = tid; i < 2048; i += 256) {
        int p   = i >> 9;
        int rem = i & 511;
        int sb  = pair0 + p;
        int r4  = rem & 255;
        const float* src = (rem < 256 ? g_Hf1 : g_Hb1) + (size_t)sb * HID;
        float4 v = ((const float4*)src)[r4];
        if (rem < 256) ((float4*)hf[p])[r4] = v;
        else           ((float4*)hb[p])[r4] = v;
    }
    __syncthreads();

    int p = tid >> 6;
    int o = tid & 63;
    if (o < OUTD) {
        int sb = pair0 + p;
        int s = sb >> 6, b = sb & 63;
        const float4* w0  = (const float4*)(Wout + (size_t)o * 2 * HID);
        const float4* w1  = w0 + 256;
        const float4* hf4 = (const float4*)hf[p];
        const float4* hb4 = (const float4*)hb[p];
        float acc = 0.f;
#pragma unroll 4
        for (int k = 0; k < 256; k++) {
            float4 a = hf4[k]; float4 w = w0[k];
            acc += a.x*w.x + a.y*w.y + a.z*w.z + a.w*w.w;
        }
#pragma unroll 4
        for (int k = 0; k < 256; k++) {
            float4 a = hb4[k]; float4 w = w1[k];
            acc += a.x*w.x + a.y*w.y + a.z*w.z + a.w*w.w;
        }
        out[((size_t)b * SEQ + s) * OUTD + o] = acc + bout[o];
    }
}

// ---------------- launch sequence ----------------
extern "C" void kernel_launch(void* const* d_in, const int* in_sizes, int n_in,
                              void* d_out, int out_size)
{
    const int*   src   = (const int*)  d_in[0];
    const float* emb   = (const float*)d_in[1];
    const float* Wih_f = (const float*)d_in[2];
    const float* Whh_f = (const float*)d_in[3];
    const float* b_f   = (const float*)d_in[4];
    const float* Wih_b = (const float*)d_in[5];
    const float* Whh_b = (const float*)d_in[6];
    const float* b_b   = (const float*)d_in[7];
    const float* Wout  = (const float*)d_in[8];
    const float* bout  = (const float*)d_in[9];
    float* out = (float*)d_out;
    (void)in_sizes; (void)n_in; (void)out_size;

    cudaFuncSetAttribute(gemm_bias_bf16,
                         cudaFuncAttributeMaxDynamicSharedMemorySize, 3 * STAGE_BYTES);

    embed_kernel<<<SEQ * BATCH * (EMB / 4) / 256, 256>>>(src, emb);

    dim3 ggrid(G4 / 128, (SEQ * BATCH) / 128);   // (32, 256)
    const int convA_blocks = (SEQ * BATCH * 1024 / 4) / 256;   // 32768
    const int convW_blocks = (G4 * 1024 / 4) / 256;            // 4096

    for (int l = 0; l < 2; l++) {
        size_t woff = (size_t)l * G4 * 1024;
        if (l == 0) {
            convA_kernel<<<convA_blocks, 256>>>(0);           // X (shared by both dirs)
            convW_kernel<<<convW_blocks, 256>>>(Wih_f + woff, 0);
            convW_kernel<<<convW_blocks, 256>>>(Wih_b + woff, 1);
            gemm_bias_bf16<<<ggrid, 256, 3 * STAGE_BYTES>>>(0, b_f + l * G4, 0);
            gemm_bias_bf16<<<ggrid, 256, 3 * STAGE_BYTES>>>(1, b_b + l * G4, 1);
        } else {
            convW_kernel<<<convW_blocks, 256>>>(Wih_f + woff, 0);
            convW_kernel<<<convW_blocks, 256>>>(Wih_b + woff, 1);
            convA_kernel<<<convA_blocks, 256>>>(1);           // Hf0
            gemm_bias_bf16<<<ggrid, 256, 3 * STAGE_BYTES>>>(0, b_f + l * G4, 0);
            convA_kernel<<<convA_blocks, 256>>>(2);           // Hb0
            gemm_bias_bf16<<<ggrid, 256, 3 * STAGE_BYTES>>>(1, b_b + l * G4, 1);
        }
        lstm_recur_kernel<<<NCTA, 256>>>(Whh_f + woff, Whh_b + woff, l);
    }

    out_kernel<<<(SEQ * BATCH) / 4, 256>>>(Wout, bout, out);
}

// round 9
// speedup vs baseline: 1.1798x; 1.0165x over previous
#include <cuda_runtime.h>
#include <cuda_fp16.h>
#include <math.h>
#include <stdint.h>

#define BATCH 64
#define SEQ   512
#define EMB   1024
#define HID   1024
#define G4    4096
#define OUTD  50
#define NCTA  128   // persistent recurrence grid

typedef unsigned long long u64;

// ---------------- static device scratch (no cudaMalloc allowed) ----------------
__device__ float g_X  [(size_t)SEQ * BATCH * EMB];
__device__ float g_Gf [(size_t)SEQ * BATCH * G4];
__device__ float g_Gb [(size_t)SEQ * BATCH * G4];
__device__ float g_Hf0[(size_t)SEQ * BATCH * HID];
__device__ float g_Hb0[(size_t)SEQ * BATCH * HID];
__device__ float g_Hf1[(size_t)SEQ * BATCH * HID];
__device__ float g_Hb1[(size_t)SEQ * BATCH * HID];
__device__ unsigned g_bar;

// fp16 planes for tensor-core GEMM: A single plane, W hi+lo (error-compensated)
__device__ __half g_Ah [(size_t)SEQ * BATCH * 1024];
__device__ __half g_Wh [2][(size_t)G4 * 1024];
__device__ __half g_Wl [2][(size_t)G4 * 1024];

// ---------------- software grid barrier ----------------
__device__ __forceinline__ void grid_sync()
{
    __syncthreads();
    if (threadIdx.x == 0) {
        __threadfence();
        unsigned ticket = atomicAdd(&g_bar, 1u);
        unsigned target = (ticket & ~(unsigned)(NCTA - 1)) + NCTA;
        while ((int)(*(volatile unsigned*)&g_bar - target) < 0) { }
        __threadfence();
    }
    __syncthreads();
}

// ---------------- packed fp32x2 helpers (Blackwell 2x FP32) ----------------
__device__ __forceinline__ u64 splat_f32x2(float v)
{
    u64 r;
    asm("mov.b64 %0, {%1, %1};" : "=l"(r) : "f"(v));
    return r;
}
__device__ __forceinline__ void fma_f32x2(u64& acc, u64 a, u64 b)
{
    asm("fma.rn.f32x2 %0, %1, %2, %0;" : "+l"(acc) : "l"(a), "l"(b));
}
__device__ __forceinline__ void unpack_f32x2(float& lo, float& hi, u64 v)
{
    asm("mov.b64 {%0, %1}, %2;" : "=f"(lo), "=f"(hi) : "l"(v));
}

// ---------------- embedding gather ----------------
__global__ void embed_kernel(const int* __restrict__ src, const float* __restrict__ emb)
{
    size_t idx = (size_t)blockIdx.x * blockDim.x + threadIdx.x;
    int    e4  = (int)(idx & (EMB / 4 - 1));
    size_t sb  = idx >> 8;
    int    b   = (int)(sb & (BATCH - 1));
    int    s   = (int)(sb >> 6);
    int    tok = src[b * SEQ + s];
    float4 v = ((const float4*)(emb + (size_t)tok * EMB))[e4];
    ((float4*)(g_X + ((size_t)s * BATCH + b) * EMB))[e4] = v;
}

// ---------------- fp32 -> fp16 conversions ----------------
__global__ void convA_kernel(int a_sel)   // A: single fp16 plane
{
    const float* A = (a_sel == 0) ? g_X : (a_sel == 1) ? g_Hf0 : g_Hb0;
    size_t i = (size_t)blockIdx.x * blockDim.x + threadIdx.x;
    float4 v = ((const float4*)A)[i];
    __half2 h01 = __floats2half2_rn(v.x, v.y);
    __half2 h23 = __floats2half2_rn(v.z, v.w);
    ((uint2*)g_Ah)[i] = make_uint2(*(unsigned*)&h01, *(unsigned*)&h23);
}

__global__ void convW_kernel(const float* __restrict__ W, int set)  // W: hi + lo planes
{
    size_t i = (size_t)blockIdx.x * blockDim.x + threadIdx.x;
    float4 v = ((const float4*)W)[i];
    __half hx = __float2half_rn(v.x), hy = __float2half_rn(v.y);
    __half hz = __float2half_rn(v.z), hw = __float2half_rn(v.w);
    __half2 h01 = __halves2half2(hx, hy), h23 = __halves2half2(hz, hw);
    __half2 l01 = __floats2half2_rn(v.x - __half2float(hx), v.y - __half2float(hy));
    __half2 l23 = __floats2half2_rn(v.z - __half2float(hz), v.w - __half2float(hw));
    ((uint2*)g_Wh[set])[i] = make_uint2(*(unsigned*)&h01, *(unsigned*)&h23);
    ((uint2*)g_Wl[set])[i] = make_uint2(*(unsigned*)&l01, *(unsigned*)&l23);
}

// ---------------- tensor-core GEMM helpers ----------------
__device__ __forceinline__ void ldsm4(unsigned* r, const __half* p)
{
    unsigned a = (unsigned)__cvta_generic_to_shared(p);
    asm volatile("ldmatrix.sync.aligned.m8n8.x4.shared.b16 {%0,%1,%2,%3}, [%4];"
                 : "=r"(r[0]), "=r"(r[1]), "=r"(r[2]), "=r"(r[3]) : "r"(a));
}

__device__ __forceinline__ void mma16816(float* c, const unsigned* a, const unsigned* b)
{
    asm volatile("mma.sync.aligned.m16n8k16.row.col.f32.f16.f16.f32 "
                 "{%0,%1,%2,%3},{%4,%5,%6,%7},{%8,%9},{%0,%1,%2,%3};"
                 : "+f"(c[0]), "+f"(c[1]), "+f"(c[2]), "+f"(c[3])
                 : "r"(a[0]), "r"(a[1]), "r"(a[2]), "r"(a[3]), "r"(b[0]), "r"(b[1]));
}

__device__ __forceinline__ void cp16(void* sdst, const void* gsrc)
{
    unsigned s = (unsigned)__cvta_generic_to_shared(sdst);
    asm volatile("cp.async.cg.shared.global [%0], [%1], 16;" :: "r"(s), "l"(gsrc) : "memory");
}

// ---------------- pipelined fp16 split-2 GEMM: C[32768][4096] = A * W^T + bias ----------------
// C = Ah*(Wh + Wl): W rounding error compensated; A fp16 rounding (~2^-13) uncompensated.
// CTA tile 128x128, k-chunk 32, 3-stage cp.async. Stage = 3 planes x 128 x 40 halfs = 30720B.
#define SROW 40
#define STAGE_ELEMS (128 * SROW)
#define STAGE_BYTES (3 * STAGE_ELEMS * 2)
__global__ void __launch_bounds__(256)
gemm_fp16(int set, const float* __restrict__ bias, int c_sel)
{
    extern __shared__ __align__(16) __half smem[];
    float* C = c_sel ? g_Gb : g_Gf;
    const __half* srcs[3] = { g_Ah, g_Wh[set], g_Wl[set] };

    const int tid    = threadIdx.x;
    const int lane   = tid & 31;
    const int wid    = tid >> 5;
    const int warp_m = wid & 3;
    const int warp_n = wid >> 2;

    const size_t rowA0 = (size_t)blockIdx.y * 128;
    const size_t rowW0 = (size_t)blockIdx.x * 128;

    const int amr = warp_m * 32 + (lane & 15);
    const int akc = (lane >> 4) << 3;
    const int wnr = warp_n * 64 + (lane & 7) + ((lane >> 4) << 3);
    const int wkc = ((lane >> 3) & 1) << 3;

    float acc[2][8][4];
#pragma unroll
    for (int i = 0; i < 2; i++)
#pragma unroll
        for (int j = 0; j < 8; j++)
#pragma unroll
            for (int q = 0; q < 4; q++) acc[i][j][q] = 0.f;

    auto load_stage = [&](int st, int k0) {
        __half* sb = smem + (size_t)st * 3 * STAGE_ELEMS;
#pragma unroll
        for (int i = 0; i < 6; i++) {
            int u = tid + 256 * i;          // 0..1535
            int plane = u >> 9;             // 512 segments per plane
            int r = (u >> 2) & 127;
            int c = u & 3;                  // 4 x 16B = 32 halfs = k-chunk
            const __half* src = srcs[plane]
                + ((plane == 0 ? rowA0 : rowW0) + r) * 1024 + k0 + c * 8;
            cp16(sb + plane * STAGE_ELEMS + r * SROW + c * 8, src);
        }
        asm volatile("cp.async.commit_group;" ::: "memory");
    };

    load_stage(0, 0);
    load_stage(1, 32);

    for (int cc = 0; cc < 32; cc++) {
        if (cc < 31) { asm volatile("cp.async.wait_group 1;" ::: "memory"); }
        else         { asm volatile("cp.async.wait_group 0;" ::: "memory"); }
        __syncthreads();
        if (cc + 2 < 32) load_stage((cc + 2) % 3, (cc + 2) * 32);

        const __half* sA = smem + (size_t)(cc % 3) * 3 * STAGE_ELEMS;
        const __half* sH = sA + STAGE_ELEMS;
        const __half* sL = sH + STAGE_ELEMS;

#pragma unroll
        for (int kk = 0; kk < 32; kk += 16) {
            unsigned Af[2][4], Wh[4][4], Wl[4][4];
#pragma unroll
            for (int mt = 0; mt < 2; mt++)
                ldsm4(Af[mt], sA + (amr + mt * 16) * SROW + akc + kk);
#pragma unroll
            for (int q = 0; q < 4; q++) {
                ldsm4(Wh[q], sH + (wnr + q * 16) * SROW + wkc + kk);
                ldsm4(Wl[q], sL + (wnr + q * 16) * SROW + wkc + kk);
            }
#pragma unroll
            for (int mt = 0; mt < 2; mt++)
#pragma unroll
                for (int nt = 0; nt < 8; nt++) {
                    mma16816(acc[mt][nt], Af[mt], &Wh[nt >> 1][(nt & 1) * 2]);
                    mma16816(acc[mt][nt], Af[mt], &Wl[nt >> 1][(nt & 1) * 2]);
                }
        }
        __syncthreads();
    }

    const int rbase = blockIdx.y * 128 + warp_m * 32 + (lane >> 2);
    const int cbase = blockIdx.x * 128 + warp_n * 64 + (lane & 3) * 2;
#pragma unroll
    for (int nt = 0; nt < 8; nt++) {
        int col = cbase + nt * 8;
        float b0 = bias[col], b1 = bias[col + 1];
#pragma unroll
        for (int mt = 0; mt < 2; mt++) {
            int r = rbase + mt * 16;
            *(float2*)(C + (size_t)r * G4 + col) =
                make_float2(acc[mt][nt][0] + b0, acc[mt][nt][1] + b1);
            *(float2*)(C + (size_t)(r + 8) * G4 + col) =
                make_float2(acc[mt][nt][2] + b0, acc[mt][nt][3] + b1);
        }
    }
}

// ---------------- persistent bidirectional LSTM recurrence (f32x2 inner loop) ----------------
__global__ void __launch_bounds__(256)
lstm_recur_kernel(const float* __restrict__ Whh_f, const float* __restrict__ Whh_b,
                  int out_sel)
{
    __shared__ __align__(16) float hs[32][64];
    __shared__ __align__(16) float ws[32][64];

    const int d  = blockIdx.x >> 6;
    const int u0 = (blockIdx.x & 63) * 16;
    const float* W     = d ? Whh_b : Whh_f;
    const float* Gd    = d ? g_Gb : g_Gf;
    float*       Hbase = out_sel ? (d ? g_Hb1 : g_Hf1) : (d ? g_Hb0 : g_Hf0);

    const int tid = threadIdx.x;
    const int tm  = tid & 15;
    const int tn  = tid >> 4;
    const int u   = u0 + tn;

    const int lm0 = tid & 63;
    const int lk0 = (tid >> 6) << 2;
    const int wrow0 = ((lm0 & 3) << 10) + u0 + (lm0 >> 2);

    float creg[4] = {0.f, 0.f, 0.f, 0.f};

    for (int t = 0; t < SEQ; t++) {
        const int sidx = d ? (SEQ - 1 - t) : t;
        const float* G    = Gd    + (size_t)sidx * BATCH * G4;
        float*       Hout = Hbase + (size_t)sidx * BATCH * HID;

        float gpre[4][4];
#pragma unroll
        for (int mi = 0; mi < 4; mi++) {
            const float* gr = G + (size_t)(tm * 4 + mi) * G4 + u;
            gpre[mi][0] = gr[0];
            gpre[mi][1] = gr[1024];
            gpre[mi][2] = gr[2048];
            gpre[mi][3] = gr[3072];
        }

        // packed accumulators: acc2[p][j] holds batches (tm*4+2p, tm*4+2p+1), gate j
        u64 acc2[2][4];
#pragma unroll
        for (int p = 0; p < 2; p++)
#pragma unroll
            for (int j = 0; j < 4; j++) acc2[p][j] = 0ull;

        if (t > 0) {
            const float* hin = Hbase + (size_t)(d ? sidx + 1 : sidx - 1) * BATCH * HID;

            float4 hv0, hv1, wv0, wv1;
            hv0 = __ldcg((const float4*)(hin + (size_t)lm0 * HID + lk0));
            hv1 = __ldcg((const float4*)(hin + (size_t)lm0 * HID + lk0 + 16));
            wv0 = *(const float4*)(W + (size_t)wrow0 * HID + lk0);
            wv1 = *(const float4*)(W + (size_t)wrow0 * HID + lk0 + 16);

            for (int k0 = 0; k0 < HID; k0 += 32) {
                __syncthreads();
                hs[lk0+0][lm0] = hv0.x; hs[lk0+1][lm0] = hv0.y; hs[lk0+2][lm0] = hv0.z; hs[lk0+3][lm0] = hv0.w;
                hs[lk0+16][lm0] = hv1.x; hs[lk0+17][lm0] = hv1.y; hs[lk0+18][lm0] = hv1.z; hs[lk0+19][lm0] = hv1.w;
                ws[lk0+0][lm0] = wv0.x; ws[lk0+1][lm0] = wv0.y; ws[lk0+2][lm0] = wv0.z; ws[lk0+3][lm0] = wv0.w;
                ws[lk0+16][lm0] = wv1.x; ws[lk0+17][lm0] = wv1.y; ws[lk0+18][lm0] = wv1.z; ws[lk0+19][lm0] = wv1.w;
                if (k0 + 32 < HID) {
                    int kn = k0 + 32;
                    hv0 = __ldcg((const float4*)(hin + (size_t)lm0 * HID + kn + lk0));
                    hv1 = __ldcg((const float4*)(hin + (size_t)lm0 * HID + kn + lk0 + 16));
                    wv0 = *(const float4*)(W + (size_t)wrow0 * HID + kn + lk0);
                    wv1 = *(const float4*)(W + (size_t)wrow0 * HID + kn + lk0 + 16);
                }
                __syncthreads();
#pragma unroll
                for (int k = 0; k < 32; k++) {
                    // a: two packed f32x2 batch-pairs, loaded directly as u64s
                    ulonglong2 av = *(const ulonglong2*)&hs[k][tm * 4];
                    float4 b = *(const float4*)&ws[k][tn * 4];
                    u64 b0 = splat_f32x2(b.x);
                    u64 b1 = splat_f32x2(b.y);
                    u64 b2 = splat_f32x2(b.z);
                    u64 b3 = splat_f32x2(b.w);
                    fma_f32x2(acc2[0][0], av.x, b0); fma_f32x2(acc2[1][0], av.y, b0);
                    fma_f32x2(acc2[0][1], av.x, b1); fma_f32x2(acc2[1][1], av.y, b1);
                    fma_f32x2(acc2[0][2], av.x, b2); fma_f32x2(acc2[1][2], av.y, b2);
                    fma_f32x2(acc2[0][3], av.x, b3); fma_f32x2(acc2[1][3], av.y, b3);
                }
            }
        }

#pragma unroll
        for (int p = 0; p < 2; p++) {
            float e0[4], e1[4];
#pragma unroll
            for (int j = 0; j < 4; j++) unpack_f32x2(e0[j], e1[j], acc2[p][j]);
#pragma unroll
            for (int h = 0; h < 2; h++) {
                int mi = 2 * p + h;
                const float* e = h ? e1 : e0;
                float gi = e[0] + gpre[mi][0];
                float gf = e[1] + gpre[mi][1];
                float gg = e[2] + gpre[mi][2];
                float go = e[3] + gpre[mi][3];
                float iv = 1.f / (1.f + expf(-gi));
                float fv = 1.f / (1.f + expf(-gf));
                float ov = 1.f / (1.f + expf(-go));
                float cn = fv * creg[mi] + iv * tanhf(gg);
                creg[mi] = cn;
                Hout[(size_t)(tm * 4 + mi) * HID + u] = ov * tanhf(cn);
            }
        }

        grid_sync();
    }
}

// ---------------- output projection ----------------
__global__ void __launch_bounds__(256)
out_kernel(const float* __restrict__ Wout, const float* __restrict__ bout,
           float* __restrict__ out)
{
    __shared__ __align__(16) float hf[4][HID];
    __shared__ __align__(16) float hb[4][HID];
    const int tid   = threadIdx.x;
    const int pair0 = blockIdx.x * 4;

    for (int i = tid; i < 2048; i += 256) {
        int p   = i >> 9;
        int rem = i & 511;
        int sb  = pair0 + p;
        int r4  = rem & 255;
        const float* src = (rem < 256 ? g_Hf1 : g_Hb1) + (size_t)sb * HID;
        float4 v = ((const float4*)src)[r4];
        if (rem < 256) ((float4*)hf[p])[r4] = v;
        else           ((float4*)hb[p])[r4] = v;
    }
    __syncthreads();

    int p = tid >> 6;
    int o = tid & 63;
    if (o < OUTD) {
        int sb = pair0 + p;
        int s = sb >> 6, b = sb & 63;
        const float4* w0  = (const float4*)(Wout + (size_t)o * 2 * HID);
        const float4* w1  = w0 + 256;
        const float4* hf4 = (const float4*)hf[p];
        const float4* hb4 = (const float4*)hb[p];
        float acc = 0.f;
#pragma unroll 4
        for (int k = 0; k < 256; k++) {
            float4 a = hf4[k]; float4 w = w0[k];
            acc += a.x*w.x + a.y*w.y + a.z*w.z + a.w*w.w;
        }
#pragma unroll 4
        for (int k = 0; k < 256; k++) {
            float4 a = hb4[k]; float4 w = w1[k];
            acc += a.x*w.x + a.y*w.y + a.z*w.z + a.w*w.w;
        }
        out[((size_t)b * SEQ + s) * OUTD + o] = acc + bout[o];
    }
}

// ---------------- launch sequence ----------------
extern "C" void kernel_launch(void* const* d_in, const int* in_sizes, int n_in,
                              void* d_out, int out_size)
{
    const int*   src   = (const int*)  d_in[0];
    const float* emb   = (const float*)d_in[1];
    const float* Wih_f = (const float*)d_in[2];
    const float* Whh_f = (const float*)d_in[3];
    const float* b_f   = (const float*)d_in[4];
    const float* Wih_b = (const float*)d_in[5];
    const float* Whh_b = (const float*)d_in[6];
    const float* b_b   = (const float*)d_in[7];
    const float* Wout  = (const float*)d_in[8];
    const float* bout  = (const float*)d_in[9];
    float* out = (float*)d_out;
    (void)in_sizes; (void)n_in; (void)out_size;

    cudaFuncSetAttribute(gemm_fp16,
                         cudaFuncAttributeMaxDynamicSharedMemorySize, 3 * STAGE_BYTES);

    embed_kernel<<<SEQ * BATCH * (EMB / 4) / 256, 256>>>(src, emb);

    dim3 ggrid(G4 / 128, (SEQ * BATCH) / 128);                 // (32, 256)
    const int convA_blocks = (SEQ * BATCH * 1024 / 4) / 256;   // 32768
    const int convW_blocks = (G4 * 1024 / 4) / 256;            // 4096

    for (int l = 0; l < 2; l++) {
        size_t woff = (size_t)l * G4 * 1024;
        if (l == 0) {
            convA_kernel<<<convA_blocks, 256>>>(0);            // X (shared by both dirs)
            convW_kernel<<<convW_blocks, 256>>>(Wih_f + woff, 0);
            convW_kernel<<<convW_blocks, 256>>>(Wih_b + woff, 1);
            gemm_fp16<<<ggrid, 256, 3 * STAGE_BYTES>>>(0, b_f + l * G4, 0);
            gemm_fp16<<<ggrid, 256, 3 * STAGE_BYTES>>>(1, b_b + l * G4, 1);
        } else {
            convW_kernel<<<convW_blocks, 256>>>(Wih_f + woff, 0);
            convW_kernel<<<convW_blocks, 256>>>(Wih_b + woff, 1);
            convA_kernel<<<convA_blocks, 256>>>(1);            // Hf0
            gemm_fp16<<<ggrid, 256, 3 * STAGE_BYTES>>>(0, b_f + l * G4, 0);
            convA_kernel<<<convA_blocks, 256>>>(2);            // Hb0
            gemm_fp16<<<ggrid, 256, 3 * STAGE_BYTES>>>(1, b_b + l * G4, 1);
        }
        lstm_recur_kernel<<<NCTA, 256>>>(Whh_f + woff, Whh_b + woff, l);
    }

    out_kernel<<<(SEQ * BATCH) / 4, 256>>>(Wout, bout, out);
}

// round 10
// speedup vs baseline: 1.3355x; 1.1320x over previous
#include <cuda_runtime.h>
#include <cuda_fp16.h>
#include <math.h>
#include <stdint.h>

#define BATCH 64
#define SEQ   512
#define EMB   1024
#define HID   1024
#define G4    4096
#define OUTD  50
#define NCTA  128   // persistent recurrence grid

typedef unsigned long long u64;

// ---------------- static device scratch (no cudaMalloc allowed) ----------------
__device__ float g_X  [(size_t)SEQ * BATCH * EMB];
__device__ float g_Gf [(size_t)SEQ * BATCH * G4];
__device__ float g_Gb [(size_t)SEQ * BATCH * G4];
__device__ float g_Hf0[(size_t)SEQ * BATCH * HID];
__device__ float g_Hb0[(size_t)SEQ * BATCH * HID];
__device__ float g_Hf1[(size_t)SEQ * BATCH * HID];
__device__ float g_Hb1[(size_t)SEQ * BATCH * HID];
__device__ unsigned g_bar;

// fp16 planes for tensor-core GEMM: A single plane, W hi+lo (error-compensated)
__device__ __half g_Ah [(size_t)SEQ * BATCH * 1024];
__device__ __half g_Wh [2][(size_t)G4 * 1024];
__device__ __half g_Wl [2][(size_t)G4 * 1024];

// ---------------- software grid barrier ----------------
__device__ __forceinline__ void grid_sync()
{
    __syncthreads();
    if (threadIdx.x == 0) {
        __threadfence();
        unsigned ticket = atomicAdd(&g_bar, 1u);
        unsigned target = (ticket & ~(unsigned)(NCTA - 1)) + NCTA;
        while ((int)(*(volatile unsigned*)&g_bar - target) < 0) { }
        __threadfence();
    }
    __syncthreads();
}

// ---------------- packed fp32x2 helpers ----------------
__device__ __forceinline__ u64 splat_f32x2(float v)
{
    u64 r;
    asm("mov.b64 %0, {%1, %1};" : "=l"(r) : "f"(v));
    return r;
}
__device__ __forceinline__ void fma_f32x2(u64& acc, u64 a, u64 b)
{
    asm("fma.rn.f32x2 %0, %1, %2, %0;" : "+l"(acc) : "l"(a), "l"(b));
}
__device__ __forceinline__ u64 add_f32x2(u64 a, u64 b)
{
    u64 r;
    asm("add.rn.f32x2 %0, %1, %2;" : "=l"(r) : "l"(a), "l"(b));
    return r;
}
__device__ __forceinline__ void unpack_f32x2(float& lo, float& hi, u64 v)
{
    asm("mov.b64 {%0, %1}, %2;" : "=f"(lo), "=f"(hi) : "l"(v));
}
__device__ __forceinline__ u64 pack_f32x2(float lo, float hi)
{
    u64 r;
    asm("mov.b64 %0, {%1, %2};" : "=l"(r) : "f"(lo), "f"(hi));
    return r;
}

// ---------------- embedding gather ----------------
__global__ void embed_kernel(const int* __restrict__ src, const float* __restrict__ emb)
{
    size_t idx = (size_t)blockIdx.x * blockDim.x + threadIdx.x;
    int    e4  = (int)(idx & (EMB / 4 - 1));
    size_t sb  = idx >> 8;
    int    b   = (int)(sb & (BATCH - 1));
    int    s   = (int)(sb >> 6);
    int    tok = src[b * SEQ + s];
    float4 v = ((const float4*)(emb + (size_t)tok * EMB))[e4];
    ((float4*)(g_X + ((size_t)s * BATCH + b) * EMB))[e4] = v;
}

// ---------------- fp32 -> fp16 conversions ----------------
__global__ void convA_kernel(int a_sel)
{
    const float* A = (a_sel == 0) ? g_X : (a_sel == 1) ? g_Hf0 : g_Hb0;
    size_t i = (size_t)blockIdx.x * blockDim.x + threadIdx.x;
    float4 v = ((const float4*)A)[i];
    __half2 h01 = __floats2half2_rn(v.x, v.y);
    __half2 h23 = __floats2half2_rn(v.z, v.w);
    ((uint2*)g_Ah)[i] = make_uint2(*(unsigned*)&h01, *(unsigned*)&h23);
}

__global__ void convW_kernel(const float* __restrict__ W, int set)
{
    size_t i = (size_t)blockIdx.x * blockDim.x + threadIdx.x;
    float4 v = ((const float4*)W)[i];
    __half hx = __float2half_rn(v.x), hy = __float2half_rn(v.y);
    __half hz = __float2half_rn(v.z), hw = __float2half_rn(v.w);
    __half2 h01 = __halves2half2(hx, hy), h23 = __halves2half2(hz, hw);
    __half2 l01 = __floats2half2_rn(v.x - __half2float(hx), v.y - __half2float(hy));
    __half2 l23 = __floats2half2_rn(v.z - __half2float(hz), v.w - __half2float(hw));
    ((uint2*)g_Wh[set])[i] = make_uint2(*(unsigned*)&h01, *(unsigned*)&h23);
    ((uint2*)g_Wl[set])[i] = make_uint2(*(unsigned*)&l01, *(unsigned*)&l23);
}

// ---------------- tensor-core GEMM helpers ----------------
__device__ __forceinline__ void ldsm4(unsigned* r, const __half* p)
{
    unsigned a = (unsigned)__cvta_generic_to_shared(p);
    asm volatile("ldmatrix.sync.aligned.m8n8.x4.shared.b16 {%0,%1,%2,%3}, [%4];"
                 : "=r"(r[0]), "=r"(r[1]), "=r"(r[2]), "=r"(r[3]) : "r"(a));
}

__device__ __forceinline__ void mma16816(float* c, const unsigned* a, const unsigned* b)
{
    asm volatile("mma.sync.aligned.m16n8k16.row.col.f32.f16.f16.f32 "
                 "{%0,%1,%2,%3},{%4,%5,%6,%7},{%8,%9},{%0,%1,%2,%3};"
                 : "+f"(c[0]), "+f"(c[1]), "+f"(c[2]), "+f"(c[3])
                 : "r"(a[0]), "r"(a[1]), "r"(a[2]), "r"(a[3]), "r"(b[0]), "r"(b[1]));
}

__device__ __forceinline__ void cp16(void* sdst, const void* gsrc)
{
    unsigned s = (unsigned)__cvta_generic_to_shared(sdst);
    asm volatile("cp.async.cg.shared.global [%0], [%1], 16;" :: "r"(s), "l"(gsrc) : "memory");
}

// ---------------- pipelined fp16 split-2 GEMM (validated in R9) ----------------
#define SROW 40
#define STAGE_ELEMS (128 * SROW)
#define STAGE_BYTES (3 * STAGE_ELEMS * 2)
__global__ void __launch_bounds__(256)
gemm_fp16(int set, const float* __restrict__ bias, int c_sel)
{
    extern __shared__ __align__(16) __half smem[];
    float* C = c_sel ? g_Gb : g_Gf;
    const __half* srcs[3] = { g_Ah, g_Wh[set], g_Wl[set] };

    const int tid    = threadIdx.x;
    const int lane   = tid & 31;
    const int wid    = tid >> 5;
    const int warp_m = wid & 3;
    const int warp_n = wid >> 2;

    const size_t rowA0 = (size_t)blockIdx.y * 128;
    const size_t rowW0 = (size_t)blockIdx.x * 128;

    const int amr = warp_m * 32 + (lane & 15);
    const int akc = (lane >> 4) << 3;
    const int wnr = warp_n * 64 + (lane & 7) + ((lane >> 4) << 3);
    const int wkc = ((lane >> 3) & 1) << 3;

    float acc[2][8][4];
#pragma unroll
    for (int i = 0; i < 2; i++)
#pragma unroll
        for (int j = 0; j < 8; j++)
#pragma unroll
            for (int q = 0; q < 4; q++) acc[i][j][q] = 0.f;

    auto load_stage = [&](int st, int k0) {
        __half* sb = smem + (size_t)st * 3 * STAGE_ELEMS;
#pragma unroll
        for (int i = 0; i < 6; i++) {
            int u = tid + 256 * i;
            int plane = u >> 9;
            int r = (u >> 2) & 127;
            int c = u & 3;
            const __half* src = srcs[plane]
                + ((plane == 0 ? rowA0 : rowW0) + r) * 1024 + k0 + c * 8;
            cp16(sb + plane * STAGE_ELEMS + r * SROW + c * 8, src);
        }
        asm volatile("cp.async.commit_group;" ::: "memory");
    };

    load_stage(0, 0);
    load_stage(1, 32);

    for (int cc = 0; cc < 32; cc++) {
        if (cc < 31) { asm volatile("cp.async.wait_group 1;" ::: "memory"); }
        else         { asm volatile("cp.async.wait_group 0;" ::: "memory"); }
        __syncthreads();
        if (cc + 2 < 32) load_stage((cc + 2) % 3, (cc + 2) * 32);

        const __half* sA = smem + (size_t)(cc % 3) * 3 * STAGE_ELEMS;
        const __half* sH = sA + STAGE_ELEMS;
        const __half* sL = sH + STAGE_ELEMS;

#pragma unroll
        for (int kk = 0; kk < 32; kk += 16) {
            unsigned Af[2][4], Wh[4][4], Wl[4][4];
#pragma unroll
            for (int mt = 0; mt < 2; mt++)
                ldsm4(Af[mt], sA + (amr + mt * 16) * SROW + akc + kk);
#pragma unroll
            for (int q = 0; q < 4; q++) {
                ldsm4(Wh[q], sH + (wnr + q * 16) * SROW + wkc + kk);
                ldsm4(Wl[q], sL + (wnr + q * 16) * SROW + wkc + kk);
            }
#pragma unroll
            for (int mt = 0; mt < 2; mt++)
#pragma unroll
                for (int nt = 0; nt < 8; nt++) {
                    mma16816(acc[mt][nt], Af[mt], &Wh[nt >> 1][(nt & 1) * 2]);
                    mma16816(acc[mt][nt], Af[mt], &Wl[nt >> 1][(nt & 1) * 2]);
                }
        }
        __syncthreads();
    }

    const int rbase = blockIdx.y * 128 + warp_m * 32 + (lane >> 2);
    const int cbase = blockIdx.x * 128 + warp_n * 64 + (lane & 3) * 2;
#pragma unroll
    for (int nt = 0; nt < 8; nt++) {
        int col = cbase + nt * 8;
        float b0 = bias[col], b1 = bias[col + 1];
#pragma unroll
        for (int mt = 0; mt < 2; mt++) {
            int r = rbase + mt * 16;
            *(float2*)(C + (size_t)r * G4 + col) =
                make_float2(acc[mt][nt][0] + b0, acc[mt][nt][1] + b1);
            *(float2*)(C + (size_t)(r + 8) * G4 + col) =
                make_float2(acc[mt][nt][2] + b0, acc[mt][nt][3] + b1);
        }
    }
}

// ---------------- persistent bidirectional LSTM recurrence ----------------
// 4 k-groups x 64 threads; per thread 8 batches x 8 cols (f32x2, 32 u64 accs);
// smem tile 16k x 64 per plane per group; partial accs reduced in aliased smem.
__global__ void __launch_bounds__(256, 1)
lstm_recur_kernel(const float* __restrict__ Whh_f, const float* __restrict__ Whh_b,
                  int out_sel)
{
    extern __shared__ __align__(16) char dsm[];
    float* tiles = (float*)dsm;       // 4 groups x (hs[16][64] + ws[16][64]) = 32KB
    u64*   red   = (u64*)dsm;         // 64KB alias, used after k-loop

    const int d  = blockIdx.x >> 6;
    const int u0 = (blockIdx.x & 63) * 16;
    const float* W     = d ? Whh_b : Whh_f;
    const float* Gd    = d ? g_Gb : g_Gf;
    float*       Hbase = out_sel ? (d ? g_Hb1 : g_Hf1) : (d ? g_Hb0 : g_Hf0);

    const int tid = threadIdx.x;
    const int grp = tid >> 6;                 // k-group, k in [grp*256, grp*256+256)
    const int t   = tid & 63;
    const int bb  = t & 7;                    // batches bb*8 .. bb*8+7
    const int cb  = t >> 3;                   // cols cb*8 .. cb*8+7
    float* hs_t = tiles + grp * 2048;         // [16][64]
    float* ws_t = hs_t + 1024;

    const int wrow = (t & 3) * 1024 + u0 + (t >> 2);   // W row for col index t
    const int kgrp = grp * 256;

    // epilogue mapping: thread handles batch-pair (b0,b0+1) x 2 u x 4 gates
    const int et  = tid >> 2;
    const int ep  = tid & 3;
    const int b0  = (et & 7) * 8 + ep * 2;
    const int eu0 = u0 + (et >> 3) * 2;

    u64 creg[2] = {0ull, 0ull};               // c for (b0,b0+1) at u = eu0+us

    for (int ts = 0; ts < SEQ; ts++) {
        const int sidx = d ? (SEQ - 1 - ts) : ts;
        const float* G = Gd + (size_t)sidx * BATCH * G4;
        float* Hout = Hbase + (size_t)sidx * BATCH * HID;

        // gpre prefetch (epilogue mapping): 16 scalars, issued before the k-loop
        float gp0[2][4], gp1[2][4];
#pragma unroll
        for (int us = 0; us < 2; us++)
#pragma unroll
            for (int gt = 0; gt < 4; gt++) {
                gp0[us][gt] = G[(size_t)b0 * G4 + gt * 1024 + eu0 + us];
                gp1[us][gt] = G[(size_t)(b0 + 1) * G4 + gt * 1024 + eu0 + us];
            }

        u64 acc2[4][8];
#pragma unroll
        for (int p = 0; p < 4; p++)
#pragma unroll
            for (int j = 0; j < 8; j++) acc2[p][j] = 0ull;

        if (ts > 0) {
            const float* hin = Hbase + (size_t)(d ? sidx + 1 : sidx - 1) * BATCH * HID;
            const float* hrow = hin + (size_t)t * HID + kgrp;
            const float* wsrc = W + (size_t)wrow * HID + kgrp;

            float4 ph[4], pw[4];
#pragma unroll
            for (int i = 0; i < 4; i++) {
                ph[i] = __ldcg((const float4*)(hrow + i * 4));
                pw[i] = *(const float4*)(wsrc + i * 4);
            }

            for (int ch = 0; ch < 16; ch++) {
                asm volatile("bar.sync %0, 64;" :: "r"(grp + 1) : "memory");
#pragma unroll
                for (int i = 0; i < 4; i++) {
                    int k4 = i * 4;
                    hs_t[(k4+0)*64 + t] = ph[i].x; hs_t[(k4+1)*64 + t] = ph[i].y;
                    hs_t[(k4+2)*64 + t] = ph[i].z; hs_t[(k4+3)*64 + t] = ph[i].w;
                    ws_t[(k4+0)*64 + t] = pw[i].x; ws_t[(k4+1)*64 + t] = pw[i].y;
                    ws_t[(k4+2)*64 + t] = pw[i].z; ws_t[(k4+3)*64 + t] = pw[i].w;
                }
                asm volatile("bar.sync %0, 64;" :: "r"(grp + 1) : "memory");
                if (ch < 15) {
                    int off = (ch + 1) * 16;
#pragma unroll
                    for (int i = 0; i < 4; i++) {
                        ph[i] = __ldcg((const float4*)(hrow + off + i * 4));
                        pw[i] = *(const float4*)(wsrc + off + i * 4);
                    }
                }
#pragma unroll
                for (int k = 0; k < 16; k++) {
                    ulonglong2 a01 = *(const ulonglong2*)&hs_t[k * 64 + bb * 8];
                    ulonglong2 a23 = *(const ulonglong2*)&hs_t[k * 64 + bb * 8 + 4];
                    float4 w0 = *(const float4*)&ws_t[k * 64 + cb * 8];
                    float4 w1 = *(const float4*)&ws_t[k * 64 + cb * 8 + 4];
                    u64 bs[8];
                    bs[0] = splat_f32x2(w0.x); bs[1] = splat_f32x2(w0.y);
                    bs[2] = splat_f32x2(w0.z); bs[3] = splat_f32x2(w0.w);
                    bs[4] = splat_f32x2(w1.x); bs[5] = splat_f32x2(w1.y);
                    bs[6] = splat_f32x2(w1.z); bs[7] = splat_f32x2(w1.w);
#pragma unroll
                    for (int j = 0; j < 8; j++) {
                        fma_f32x2(acc2[0][j], a01.x, bs[j]);
                        fma_f32x2(acc2[1][j], a01.y, bs[j]);
                        fma_f32x2(acc2[2][j], a23.x, bs[j]);
                        fma_f32x2(acc2[3][j], a23.y, bs[j]);
                    }
                }
            }
        }

        // ---- reduce the 4 k-group partials ----
        __syncthreads();
        {
            u64* dst = red + (size_t)tid * 32;
#pragma unroll
            for (int p = 0; p < 4; p++)
#pragma unroll
                for (int j = 0; j < 8; j += 2)
                    *(ulonglong2*)&dst[p * 8 + j] = make_ulonglong2(acc2[p][j], acc2[p][j + 1]);
        }
        __syncthreads();

        u64 s[8];
        {
            const u64* src0 = red + ((size_t)(0 * 64 + et) * 32 + ep * 8);
#pragma unroll
            for (int j = 0; j < 8; j += 2) {
                ulonglong2 v = *(const ulonglong2*)&src0[j];
                s[j] = v.x; s[j + 1] = v.y;
            }
#pragma unroll
            for (int g = 1; g < 4; g++) {
                const u64* srcg = red + ((size_t)(g * 64 + et) * 32 + ep * 8);
#pragma unroll
                for (int j = 0; j < 8; j += 2) {
                    ulonglong2 v = *(const ulonglong2*)&srcg[j];
                    s[j] = add_f32x2(s[j], v.x);
                    s[j + 1] = add_f32x2(s[j + 1], v.y);
                }
            }
        }

        // ---- activations + c update + h write ----
#pragma unroll
        for (int us = 0; us < 2; us++) {
            float gi0, gi1, gf0, gf1, gg0, gg1, go0, go1;
            unpack_f32x2(gi0, gi1, s[us * 4 + 0]);
            unpack_f32x2(gf0, gf1, s[us * 4 + 1]);
            unpack_f32x2(gg0, gg1, s[us * 4 + 2]);
            unpack_f32x2(go0, go1, s[us * 4 + 3]);
            gi0 += gp0[us][0]; gi1 += gp1[us][0];
            gf0 += gp0[us][1]; gf1 += gp1[us][1];
            gg0 += gp0[us][2]; gg1 += gp1[us][2];
            go0 += gp0[us][3]; go1 += gp1[us][3];
            float c0, c1;
            unpack_f32x2(c0, c1, creg[us]);
            float iv0 = 1.f / (1.f + expf(-gi0)), iv1 = 1.f / (1.f + expf(-gi1));
            float fv0 = 1.f / (1.f + expf(-gf0)), fv1 = 1.f / (1.f + expf(-gf1));
            float ov0 = 1.f / (1.f + expf(-go0)), ov1 = 1.f / (1.f + expf(-go1));
            float cn0 = fv0 * c0 + iv0 * tanhf(gg0);
            float cn1 = fv1 * c1 + iv1 * tanhf(gg1);
            creg[us] = pack_f32x2(cn0, cn1);
            int u = eu0 + us;
            Hout[(size_t)b0 * HID + u]       = ov0 * tanhf(cn0);
            Hout[(size_t)(b0 + 1) * HID + u] = ov1 * tanhf(cn1);
        }

        grid_sync();
    }
}

// ---------------- output projection ----------------
__global__ void __launch_bounds__(256)
out_kernel(const float* __restrict__ Wout, const float* __restrict__ bout,
           float* __restrict__ out)
{
    __shared__ __align__(16) float hf[4][HID];
    __shared__ __align__(16) float hb[4][HID];
    const int tid   = threadIdx.x;
    const int pair0 = blockIdx.x * 4;

    for (int i = tid; i < 2048; i += 256) {
        int p   = i >> 9;
        int rem = i & 511;
        int sb  = pair0 + p;
        int r4  = rem & 255;
        const float* src = (rem < 256 ? g_Hf1 : g_Hb1) + (size_t)sb * HID;
        float4 v = ((const float4*)src)[r4];
        if (rem < 256) ((float4*)hf[p])[r4] = v;
        else           ((float4*)hb[p])[r4] = v;
    }
    __syncthreads();

    int p = tid >> 6;
    int o = tid & 63;
    if (o < OUTD) {
        int sb = pair0 + p;
        int s = sb >> 6, b = sb & 63;
        const float4* w0  = (const float4*)(Wout + (size_t)o * 2 * HID);
        const float4* w1  = w0 + 256;
        const float4* hf4 = (const float4*)hf[p];
        const float4* hb4 = (const float4*)hb[p];
        float acc = 0.f;
#pragma unroll 4
        for (int k = 0; k < 256; k++) {
            float4 a = hf4[k]; float4 w = w0[k];
            acc += a.x*w.x + a.y*w.y + a.z*w.z + a.w*w.w;
        }
#pragma unroll 4
        for (int k = 0; k < 256; k++) {
            float4 a = hb4[k]; float4 w = w1[k];
            acc += a.x*w.x + a.y*w.y + a.z*w.z + a.w*w.w;
        }
        out[((size_t)b * SEQ + s) * OUTD + o] = acc + bout[o];
    }
}

// ---------------- launch sequence ----------------
extern "C" void kernel_launch(void* const* d_in, const int* in_sizes, int n_in,
                              void* d_out, int out_size)
{
    const int*   src   = (const int*)  d_in[0];
    const float* emb   = (const float*)d_in[1];
    const float* Wih_f = (const float*)d_in[2];
    const float* Whh_f = (const float*)d_in[3];
    const float* b_f   = (const float*)d_in[4];
    const float* Wih_b = (const float*)d_in[5];
    const float* Whh_b = (const float*)d_in[6];
    const float* b_b   = (const float*)d_in[7];
    const float* Wout  = (const float*)d_in[8];
    const float* bout  = (const float*)d_in[9];
    float* out = (float*)d_out;
    (void)in_sizes; (void)n_in; (void)out_size;

    cudaFuncSetAttribute(gemm_fp16,
                         cudaFuncAttributeMaxDynamicSharedMemorySize, 3 * STAGE_BYTES);
    cudaFuncSetAttribute(lstm_recur_kernel,
                         cudaFuncAttributeMaxDynamicSharedMemorySize, 65536);

    embed_kernel<<<SEQ * BATCH * (EMB / 4) / 256, 256>>>(src, emb);

    dim3 ggrid(G4 / 128, (SEQ * BATCH) / 128);                 // (32, 256)
    const int convA_blocks = (SEQ * BATCH * 1024 / 4) / 256;   // 32768
    const int convW_blocks = (G4 * 1024 / 4) / 256;            // 4096

    for (int l = 0; l < 2; l++) {
        size_t woff = (size_t)l * G4 * 1024;
        if (l == 0) {
            convA_kernel<<<convA_blocks, 256>>>(0);            // X (shared by both dirs)
            convW_kernel<<<convW_blocks, 256>>>(Wih_f + woff, 0);
            convW_kernel<<<convW_blocks, 256>>>(Wih_b + woff, 1);
            gemm_fp16<<<ggrid, 256, 3 * STAGE_BYTES>>>(0, b_f + l * G4, 0);
            gemm_fp16<<<ggrid, 256, 3 * STAGE_BYTES>>>(1, b_b + l * G4, 1);
        } else {
            convW_kernel<<<convW_blocks, 256>>>(Wih_f + woff, 0);
            convW_kernel<<<convW_blocks, 256>>>(Wih_b + woff, 1);
            convA_kernel<<<convA_blocks, 256>>>(1);            // Hf0
            gemm_fp16<<<ggrid, 256, 3 * STAGE_BYTES>>>(0, b_f + l * G4, 0);
            convA_kernel<<<convA_blocks, 256>>>(2);            // Hb0
            gemm_fp16<<<ggrid, 256, 3 * STAGE_BYTES>>>(1, b_b + l * G4, 1);
        }
        lstm_recur_kernel<<<NCTA, 256, 65536>>>(Whh_f + woff, Whh_b + woff, l);
    }

    out_kernel<<<(SEQ * BATCH) / 4, 256>>>(Wout, bout, out);
}

// round 11
// speedup vs baseline: 1.4235x; 1.0659x over previous
#include <cuda_runtime.h>
#include <cuda_fp16.h>
#include <math.h>
#include <stdint.h>

#define BATCH 64
#define SEQ   512
#define EMB   1024
#define HID   1024
#define G4    4096
#define OUTD  50
#define NCTA  128   // persistent recurrence grid

typedef unsigned long long u64;

// ---------------- static device scratch (no cudaMalloc allowed) ----------------
__device__ float g_Gf [(size_t)SEQ * BATCH * G4];
__device__ float g_Gb [(size_t)SEQ * BATCH * G4];
__device__ float g_Hf0[(size_t)SEQ * BATCH * HID];
__device__ float g_Hb0[(size_t)SEQ * BATCH * HID];
__device__ float g_Hf1[(size_t)SEQ * BATCH * HID];
__device__ float g_Hb1[(size_t)SEQ * BATCH * HID];
__device__ unsigned g_bar;

// fp16 A planes: g_Ah = embedded X; g_Ahf/g_Ahb = layer0 h (written by recurrence)
__device__ __half g_Ah [(size_t)SEQ * BATCH * 1024];
__device__ __half g_Ahf[(size_t)SEQ * BATCH * 1024];
__device__ __half g_Ahb[(size_t)SEQ * BATCH * 1024];
__device__ __half g_Wh [2][(size_t)G4 * 1024];

// ---------------- software grid barrier ----------------
__device__ __forceinline__ void grid_sync()
{
    __syncthreads();
    if (threadIdx.x == 0) {
        __threadfence();
        unsigned ticket = atomicAdd(&g_bar, 1u);
        unsigned target = (ticket & ~(unsigned)(NCTA - 1)) + NCTA;
        while ((int)(*(volatile unsigned*)&g_bar - target) < 0) { }
        __threadfence();
    }
    __syncthreads();
}

// ---------------- packed fp32x2 helpers ----------------
__device__ __forceinline__ u64 splat_f32x2(float v)
{
    u64 r;
    asm("mov.b64 %0, {%1, %1};" : "=l"(r) : "f"(v));
    return r;
}
__device__ __forceinline__ void fma_f32x2(u64& acc, u64 a, u64 b)
{
    asm("fma.rn.f32x2 %0, %1, %2, %0;" : "+l"(acc) : "l"(a), "l"(b));
}
__device__ __forceinline__ u64 add_f32x2(u64 a, u64 b)
{
    u64 r;
    asm("add.rn.f32x2 %0, %1, %2;" : "=l"(r) : "l"(a), "l"(b));
    return r;
}
__device__ __forceinline__ void unpack_f32x2(float& lo, float& hi, u64 v)
{
    asm("mov.b64 {%0, %1}, %2;" : "=f"(lo), "=f"(hi) : "l"(v));
}
__device__ __forceinline__ u64 pack_f32x2(float lo, float hi)
{
    u64 r;
    asm("mov.b64 %0, {%1, %2};" : "=l"(r) : "f"(lo), "f"(hi));
    return r;
}

// ---------------- embedding gather: writes fp16 A plane directly ----------------
__global__ void embed_kernel(const int* __restrict__ src, const float* __restrict__ emb)
{
    size_t idx = (size_t)blockIdx.x * blockDim.x + threadIdx.x;   // over S*B*(E/4)
    int    e4  = (int)(idx & (EMB / 4 - 1));
    size_t sb  = idx >> 8;
    int    b   = (int)(sb & (BATCH - 1));
    int    s   = (int)(sb >> 6);
    int    tok = src[b * SEQ + s];
    float4 v = ((const float4*)(emb + (size_t)tok * EMB))[e4];
    __half2 h01 = __floats2half2_rn(v.x, v.y);
    __half2 h23 = __floats2half2_rn(v.z, v.w);
    ((uint2*)g_Ah)[idx] = make_uint2(*(unsigned*)&h01, *(unsigned*)&h23);
}

// ---------------- fp32 -> fp16 W conversion (single plane) ----------------
__global__ void convW_kernel(const float* __restrict__ W, int set)
{
    size_t i = (size_t)blockIdx.x * blockDim.x + threadIdx.x;
    float4 v = ((const float4*)W)[i];
    __half2 h01 = __floats2half2_rn(v.x, v.y);
    __half2 h23 = __floats2half2_rn(v.z, v.w);
    ((uint2*)g_Wh[set])[i] = make_uint2(*(unsigned*)&h01, *(unsigned*)&h23);
}

// ---------------- tensor-core GEMM helpers ----------------
__device__ __forceinline__ void ldsm4(unsigned* r, const __half* p)
{
    unsigned a = (unsigned)__cvta_generic_to_shared(p);
    asm volatile("ldmatrix.sync.aligned.m8n8.x4.shared.b16 {%0,%1,%2,%3}, [%4];"
                 : "=r"(r[0]), "=r"(r[1]), "=r"(r[2]), "=r"(r[3]) : "r"(a));
}

__device__ __forceinline__ void mma16816(float* c, const unsigned* a, const unsigned* b)
{
    asm volatile("mma.sync.aligned.m16n8k16.row.col.f32.f16.f16.f32 "
                 "{%0,%1,%2,%3},{%4,%5,%6,%7},{%8,%9},{%0,%1,%2,%3};"
                 : "+f"(c[0]), "+f"(c[1]), "+f"(c[2]), "+f"(c[3])
                 : "r"(a[0]), "r"(a[1]), "r"(a[2]), "r"(a[3]), "r"(b[0]), "r"(b[1]));
}

__device__ __forceinline__ void cp16(void* sdst, const void* gsrc)
{
    unsigned s = (unsigned)__cvta_generic_to_shared(sdst);
    asm volatile("cp.async.cg.shared.global [%0], [%1], 16;" :: "r"(s), "l"(gsrc) : "memory");
}

// ---------------- pipelined fp16 GEMM: C[32768][4096] = A * W^T + bias ----------------
// Single fp16 plane each side. CTA tile 128x128, k-chunk 32, 3-stage cp.async.
// Stage = 2 planes x 128 x 40 halfs = 20480B; 3 stages = 60KB -> 2 CTAs/SM.
#define SROW 40
#define STAGE_ELEMS (128 * SROW)
#define STAGE_BYTES (2 * STAGE_ELEMS * 2)
__global__ void __launch_bounds__(256, 2)
gemm_fp16(int a_sel, int set, const float* __restrict__ bias, int c_sel)
{
    extern __shared__ __align__(16) __half smem[];
    float* C = c_sel ? g_Gb : g_Gf;
    const __half* Apl = (a_sel == 0) ? g_Ah : (a_sel == 1) ? g_Ahf : g_Ahb;
    const __half* Wpl = g_Wh[set];

    const int tid    = threadIdx.x;
    const int lane   = tid & 31;
    const int wid    = tid >> 5;
    const int warp_m = wid & 3;
    const int warp_n = wid >> 2;

    const size_t rowA0 = (size_t)blockIdx.y * 128;
    const size_t rowW0 = (size_t)blockIdx.x * 128;

    const int amr = warp_m * 32 + (lane & 15);
    const int akc = (lane >> 4) << 3;
    const int wnr = warp_n * 64 + (lane & 7) + ((lane >> 4) << 3);
    const int wkc = ((lane >> 3) & 1) << 3;

    float acc[2][8][4];
#pragma unroll
    for (int i = 0; i < 2; i++)
#pragma unroll
        for (int j = 0; j < 8; j++)
#pragma unroll
            for (int q = 0; q < 4; q++) acc[i][j][q] = 0.f;

    auto load_stage = [&](int st, int k0) {
        __half* sb = smem + (size_t)st * 2 * STAGE_ELEMS;
#pragma unroll
        for (int i = 0; i < 4; i++) {
            int u = tid + 256 * i;          // 0..1023
            int plane = u >> 9;             // 0=A, 1=W
            int r = (u >> 2) & 127;
            int c = u & 3;
            const __half* src = (plane == 0 ? Apl + (rowA0 + r) * 1024
                                            : Wpl + (rowW0 + r) * 1024) + k0 + c * 8;
            cp16(sb + plane * STAGE_ELEMS + r * SROW + c * 8, src);
        }
        asm volatile("cp.async.commit_group;" ::: "memory");
    };

    load_stage(0, 0);
    load_stage(1, 32);

    for (int cc = 0; cc < 32; cc++) {
        if (cc < 31) { asm volatile("cp.async.wait_group 1;" ::: "memory"); }
        else         { asm volatile("cp.async.wait_group 0;" ::: "memory"); }
        __syncthreads();
        if (cc + 2 < 32) load_stage((cc + 2) % 3, (cc + 2) * 32);

        const __half* sA = smem + (size_t)(cc % 3) * 2 * STAGE_ELEMS;
        const __half* sW = sA + STAGE_ELEMS;

#pragma unroll
        for (int kk = 0; kk < 32; kk += 16) {
            unsigned Af[2][4], Wf[4][4];
#pragma unroll
            for (int mt = 0; mt < 2; mt++)
                ldsm4(Af[mt], sA + (amr + mt * 16) * SROW + akc + kk);
#pragma unroll
            for (int q = 0; q < 4; q++)
                ldsm4(Wf[q], sW + (wnr + q * 16) * SROW + wkc + kk);
#pragma unroll
            for (int mt = 0; mt < 2; mt++)
#pragma unroll
                for (int nt = 0; nt < 8; nt++)
                    mma16816(acc[mt][nt], Af[mt], &Wf[nt >> 1][(nt & 1) * 2]);
        }
        __syncthreads();
    }

    const int rbase = blockIdx.y * 128 + warp_m * 32 + (lane >> 2);
    const int cbase = blockIdx.x * 128 + warp_n * 64 + (lane & 3) * 2;
#pragma unroll
    for (int nt = 0; nt < 8; nt++) {
        int col = cbase + nt * 8;
        float b0 = bias[col], b1 = bias[col + 1];
#pragma unroll
        for (int mt = 0; mt < 2; mt++) {
            int r = rbase + mt * 16;
            *(float2*)(C + (size_t)r * G4 + col) =
                make_float2(acc[mt][nt][0] + b0, acc[mt][nt][1] + b1);
            *(float2*)(C + (size_t)(r + 8) * G4 + col) =
                make_float2(acc[mt][nt][2] + b0, acc[mt][nt][3] + b1);
        }
    }
}

// ---------------- persistent bidirectional LSTM recurrence (validated R10) ----------------
// 4 k-groups x 64 threads; per thread 8 batches x 8 cols (f32x2 accs);
// layer0 additionally mirrors h into fp16 A planes for the layer1 GEMMs.
__global__ void __launch_bounds__(256, 1)
lstm_recur_kernel(const float* __restrict__ Whh_f, const float* __restrict__ Whh_b,
                  int out_sel)
{
    extern __shared__ __align__(16) char dsm[];
    float* tiles = (float*)dsm;       // 4 groups x (hs[16][64] + ws[16][64]) = 32KB
    u64*   red   = (u64*)dsm;         // 64KB alias, used after k-loop

    const int d  = blockIdx.x >> 6;
    const int u0 = (blockIdx.x & 63) * 16;
    const float* W     = d ? Whh_b : Whh_f;
    const float* Gd    = d ? g_Gb : g_Gf;
    float*       Hbase = out_sel ? (d ? g_Hb1 : g_Hf1) : (d ? g_Hb0 : g_Hf0);
    __half*      A16   = d ? g_Ahb : g_Ahf;   // fp16 mirror (layer0 only)

    const int tid = threadIdx.x;
    const int grp = tid >> 6;
    const int t   = tid & 63;
    const int bb  = t & 7;
    const int cb  = t >> 3;
    float* hs_t = tiles + grp * 2048;
    float* ws_t = hs_t + 1024;

    const int wrow = (t & 3) * 1024 + u0 + (t >> 2);
    const int kgrp = grp * 256;

    const int et  = tid >> 2;
    const int ep  = tid & 3;
    const int b0  = (et & 7) * 8 + ep * 2;
    const int eu0 = u0 + (et >> 3) * 2;

    u64 creg[2] = {0ull, 0ull};

    for (int ts = 0; ts < SEQ; ts++) {
        const int sidx = d ? (SEQ - 1 - ts) : ts;
        const float* G = Gd + (size_t)sidx * BATCH * G4;
        float* Hout = Hbase + (size_t)sidx * BATCH * HID;

        float gp0[2][4], gp1[2][4];
#pragma unroll
        for (int us = 0; us < 2; us++)
#pragma unroll
            for (int gt = 0; gt < 4; gt++) {
                gp0[us][gt] = G[(size_t)b0 * G4 + gt * 1024 + eu0 + us];
                gp1[us][gt] = G[(size_t)(b0 + 1) * G4 + gt * 1024 + eu0 + us];
            }

        u64 acc2[4][8];
#pragma unroll
        for (int p = 0; p < 4; p++)
#pragma unroll
            for (int j = 0; j < 8; j++) acc2[p][j] = 0ull;

        if (ts > 0) {
            const float* hin = Hbase + (size_t)(d ? sidx + 1 : sidx - 1) * BATCH * HID;
            const float* hrow = hin + (size_t)t * HID + kgrp;
            const float* wsrc = W + (size_t)wrow * HID + kgrp;

            float4 ph[4], pw[4];
#pragma unroll
            for (int i = 0; i < 4; i++) {
                ph[i] = __ldcg((const float4*)(hrow + i * 4));
                pw[i] = *(const float4*)(wsrc + i * 4);
            }

            for (int ch = 0; ch < 16; ch++) {
                asm volatile("bar.sync %0, 64;" :: "r"(grp + 1) : "memory");
#pragma unroll
                for (int i = 0; i < 4; i++) {
                    int k4 = i * 4;
                    hs_t[(k4+0)*64 + t] = ph[i].x; hs_t[(k4+1)*64 + t] = ph[i].y;
                    hs_t[(k4+2)*64 + t] = ph[i].z; hs_t[(k4+3)*64 + t] = ph[i].w;
                    ws_t[(k4+0)*64 + t] = pw[i].x; ws_t[(k4+1)*64 + t] = pw[i].y;
                    ws_t[(k4+2)*64 + t] = pw[i].z; ws_t[(k4+3)*64 + t] = pw[i].w;
                }
                asm volatile("bar.sync %0, 64;" :: "r"(grp + 1) : "memory");
                if (ch < 15) {
                    int off = (ch + 1) * 16;
#pragma unroll
                    for (int i = 0; i < 4; i++) {
                        ph[i] = __ldcg((const float4*)(hrow + off + i * 4));
                        pw[i] = *(const float4*)(wsrc + off + i * 4);
                    }
                }
#pragma unroll
                for (int k = 0; k < 16; k++) {
                    ulonglong2 a01 = *(const ulonglong2*)&hs_t[k * 64 + bb * 8];
                    ulonglong2 a23 = *(const ulonglong2*)&hs_t[k * 64 + bb * 8 + 4];
                    float4 w0 = *(const float4*)&ws_t[k * 64 + cb * 8];
                    float4 w1 = *(const float4*)&ws_t[k * 64 + cb * 8 + 4];
                    u64 bs[8];
                    bs[0] = splat_f32x2(w0.x); bs[1] = splat_f32x2(w0.y);
                    bs[2] = splat_f32x2(w0.z); bs[3] = splat_f32x2(w0.w);
                    bs[4] = splat_f32x2(w1.x); bs[5] = splat_f32x2(w1.y);
                    bs[6] = splat_f32x2(w1.z); bs[7] = splat_f32x2(w1.w);
#pragma unroll
                    for (int j = 0; j < 8; j++) {
                        fma_f32x2(acc2[0][j], a01.x, bs[j]);
                        fma_f32x2(acc2[1][j], a01.y, bs[j]);
                        fma_f32x2(acc2[2][j], a23.x, bs[j]);
                        fma_f32x2(acc2[3][j], a23.y, bs[j]);
                    }
                }
            }
        }

        // ---- reduce the 4 k-group partials ----
        __syncthreads();
        {
            u64* dst = red + (size_t)tid * 32;
#pragma unroll
            for (int p = 0; p < 4; p++)
#pragma unroll
                for (int j = 0; j < 8; j += 2)
                    *(ulonglong2*)&dst[p * 8 + j] = make_ulonglong2(acc2[p][j], acc2[p][j + 1]);
        }
        __syncthreads();

        u64 s[8];
        {
            const u64* src0 = red + ((size_t)(0 * 64 + et) * 32 + ep * 8);
#pragma unroll
            for (int j = 0; j < 8; j += 2) {
                ulonglong2 v = *(const ulonglong2*)&src0[j];
                s[j] = v.x; s[j + 1] = v.y;
            }
#pragma unroll
            for (int g = 1; g < 4; g++) {
                const u64* srcg = red + ((size_t)(g * 64 + et) * 32 + ep * 8);
#pragma unroll
                for (int j = 0; j < 8; j += 2) {
                    ulonglong2 v = *(const ulonglong2*)&srcg[j];
                    s[j] = add_f32x2(s[j], v.x);
                    s[j + 1] = add_f32x2(s[j + 1], v.y);
                }
            }
        }

        // ---- activations + c update + h write (+ fp16 mirror for layer0) ----
        __half* arow = A16 + (size_t)sidx * BATCH * HID;
#pragma unroll
        for (int us = 0; us < 2; us++) {
            float gi0, gi1, gf0, gf1, gg0, gg1, go0, go1;
            unpack_f32x2(gi0, gi1, s[us * 4 + 0]);
            unpack_f32x2(gf0, gf1, s[us * 4 + 1]);
            unpack_f32x2(gg0, gg1, s[us * 4 + 2]);
            unpack_f32x2(go0, go1, s[us * 4 + 3]);
            gi0 += gp0[us][0]; gi1 += gp1[us][0];
            gf0 += gp0[us][1]; gf1 += gp1[us][1];
            gg0 += gp0[us][2]; gg1 += gp1[us][2];
            go0 += gp0[us][3]; go1 += gp1[us][3];
            float c0, c1;
            unpack_f32x2(c0, c1, creg[us]);
            float iv0 = 1.f / (1.f + expf(-gi0)), iv1 = 1.f / (1.f + expf(-gi1));
            float fv0 = 1.f / (1.f + expf(-gf0)), fv1 = 1.f / (1.f + expf(-gf1));
            float ov0 = 1.f / (1.f + expf(-go0)), ov1 = 1.f / (1.f + expf(-go1));
            float cn0 = fv0 * c0 + iv0 * tanhf(gg0);
            float cn1 = fv1 * c1 + iv1 * tanhf(gg1);
            creg[us] = pack_f32x2(cn0, cn1);
            int u = eu0 + us;
            float h0v = ov0 * tanhf(cn0);
            float h1v = ov1 * tanhf(cn1);
            Hout[(size_t)b0 * HID + u]       = h0v;
            Hout[(size_t)(b0 + 1) * HID + u] = h1v;
            if (out_sel == 0) {
                arow[(size_t)b0 * HID + u]       = __float2half_rn(h0v);
                arow[(size_t)(b0 + 1) * HID + u] = __float2half_rn(h1v);
            }
        }

        grid_sync();
    }
}

// ---------------- output projection ----------------
__global__ void __launch_bounds__(256)
out_kernel(const float* __restrict__ Wout, const float* __restrict__ bout,
           float* __restrict__ out)
{
    __shared__ __align__(16) float hf[4][HID];
    __shared__ __align__(16) float hb[4][HID];
    const int tid   = threadIdx.x;
    const int pair0 = blockIdx.x * 4;

    for (int i = tid; i < 2048; i += 256) {
        int p   = i >> 9;
        int rem = i & 511;
        int sb  = pair0 + p;
        int r4  = rem & 255;
        const float* src = (rem < 256 ? g_Hf1 : g_Hb1) + (size_t)sb * HID;
        float4 v = ((const float4*)src)[r4];
        if (rem < 256) ((float4*)hf[p])[r4] = v;
        else           ((float4*)hb[p])[r4] = v;
    }
    __syncthreads();

    int p = tid >> 6;
    int o = tid & 63;
    if (o < OUTD) {
        int sb = pair0 + p;
        int s = sb >> 6, b = sb & 63;
        const float4* w0  = (const float4*)(Wout + (size_t)o * 2 * HID);
        const float4* w1  = w0 + 256;
        const float4* hf4 = (const float4*)hf[p];
        const float4* hb4 = (const float4*)hb[p];
        float acc = 0.f;
#pragma unroll 4
        for (int k = 0; k < 256; k++) {
            float4 a = hf4[k]; float4 w = w0[k];
            acc += a.x*w.x + a.y*w.y + a.z*w.z + a.w*w.w;
        }
#pragma unroll 4
        for (int k = 0; k < 256; k++) {
            float4 a = hb4[k]; float4 w = w1[k];
            acc += a.x*w.x + a.y*w.y + a.z*w.z + a.w*w.w;
        }
        out[((size_t)b * SEQ + s) * OUTD + o] = acc + bout[o];
    }
}

// ---------------- launch sequence ----------------
extern "C" void kernel_launch(void* const* d_in, const int* in_sizes, int n_in,
                              void* d_out, int out_size)
{
    const int*   src   = (const int*)  d_in[0];
    const float* emb   = (const float*)d_in[1];
    const float* Wih_f = (const float*)d_in[2];
    const float* Whh_f = (const float*)d_in[3];
    const float* b_f   = (const float*)d_in[4];
    const float* Wih_b = (const float*)d_in[5];
    const float* Whh_b = (const float*)d_in[6];
    const float* b_b   = (const float*)d_in[7];
    const float* Wout  = (const float*)d_in[8];
    const float* bout  = (const float*)d_in[9];
    float* out = (float*)d_out;
    (void)in_sizes; (void)n_in; (void)out_size;

    cudaFuncSetAttribute(gemm_fp16,
                         cudaFuncAttributeMaxDynamicSharedMemorySize, 3 * STAGE_BYTES);
    cudaFuncSetAttribute(lstm_recur_kernel,
                         cudaFuncAttributeMaxDynamicSharedMemorySize, 65536);

    embed_kernel<<<SEQ * BATCH * (EMB / 4) / 256, 256>>>(src, emb);

    dim3 ggrid(G4 / 128, (SEQ * BATCH) / 128);                 // (32, 256)
    const int convW_blocks = (G4 * 1024 / 4) / 256;            // 4096

    for (int l = 0; l < 2; l++) {
        size_t woff = (size_t)l * G4 * 1024;
        int a_f = (l == 0) ? 0 : 1;   // X or Hf0-fp16
        int a_b = (l == 0) ? 0 : 2;   // X or Hb0-fp16
        convW_kernel<<<convW_blocks, 256>>>(Wih_f + woff, 0);
        convW_kernel<<<convW_blocks, 256>>>(Wih_b + woff, 1);
        gemm_fp16<<<ggrid, 256, 3 * STAGE_BYTES>>>(a_f, 0, b_f + l * G4, 0);
        gemm_fp16<<<ggrid, 256, 3 * STAGE_BYTES>>>(a_b, 1, b_b + l * G4, 1);
        lstm_recur_kernel<<<NCTA, 256, 65536>>>(Whh_f + woff, Whh_b + woff, l);
    }

    out_kernel<<<(SEQ * BATCH) / 4, 256>>>(Wout, bout, out);
}

// round 12
// speedup vs baseline: 4.4566x; 3.1307x over previous
#include <cuda_runtime.h>
#include <cuda_fp16.h>
#include <math.h>
#include <stdint.h>

#define BATCH 64
#define SEQ   512
#define EMB   1024
#define HID   1024
#define G4    4096
#define OUTD  50
#define NCTA  128   // persistent recurrence grid

// ---------------- static device scratch (no cudaMalloc allowed) ----------------
__device__ float g_Gf [(size_t)SEQ * BATCH * G4];
__device__ float g_Gb [(size_t)SEQ * BATCH * G4];
__device__ float g_Hf1[(size_t)SEQ * BATCH * HID];
__device__ float g_Hb1[(size_t)SEQ * BATCH * HID];
__device__ unsigned g_bar;

// fp16 planes: g_Ah = embedded X; g_Ahf/g_Ahb = layer0 h (GEMM input + recurrence state);
// g_B1f/g_B1b = layer1 h state. g_Wh = Wih fp16.
__device__ __half g_Ah [(size_t)SEQ * BATCH * 1024];
__device__ __half g_Ahf[(size_t)SEQ * BATCH * 1024];
__device__ __half g_Ahb[(size_t)SEQ * BATCH * 1024];
__device__ __half g_B1f[(size_t)SEQ * BATCH * 1024];
__device__ __half g_B1b[(size_t)SEQ * BATCH * 1024];
__device__ __half g_Wh [2][(size_t)G4 * 1024];

// ---------------- software grid barrier ----------------
__device__ __forceinline__ void grid_sync()
{
    __syncthreads();
    if (threadIdx.x == 0) {
        __threadfence();
        unsigned ticket = atomicAdd(&g_bar, 1u);
        unsigned target = (ticket & ~(unsigned)(NCTA - 1)) + NCTA;
        while ((int)(*(volatile unsigned*)&g_bar - target) < 0) { }
        __threadfence();
    }
    __syncthreads();
}

// ---------------- embedding gather: writes fp16 A plane directly ----------------
__global__ void embed_kernel(const int* __restrict__ src, const float* __restrict__ emb)
{
    size_t idx = (size_t)blockIdx.x * blockDim.x + threadIdx.x;
    int    e4  = (int)(idx & (EMB / 4 - 1));
    size_t sb  = idx >> 8;
    int    b   = (int)(sb & (BATCH - 1));
    int    s   = (int)(sb >> 6);
    int    tok = src[b * SEQ + s];
    float4 v = ((const float4*)(emb + (size_t)tok * EMB))[e4];
    __half2 h01 = __floats2half2_rn(v.x, v.y);
    __half2 h23 = __floats2half2_rn(v.z, v.w);
    ((uint2*)g_Ah)[idx] = make_uint2(*(unsigned*)&h01, *(unsigned*)&h23);
}

// ---------------- fp32 -> fp16 W conversion ----------------
__global__ void convW_kernel(const float* __restrict__ W, int set)
{
    size_t i = (size_t)blockIdx.x * blockDim.x + threadIdx.x;
    float4 v = ((const float4*)W)[i];
    __half2 h01 = __floats2half2_rn(v.x, v.y);
    __half2 h23 = __floats2half2_rn(v.z, v.w);
    ((uint2*)g_Wh[set])[i] = make_uint2(*(unsigned*)&h01, *(unsigned*)&h23);
}

// ---------------- tensor-core helpers ----------------
__device__ __forceinline__ void ldsm4(unsigned* r, const __half* p)
{
    unsigned a = (unsigned)__cvta_generic_to_shared(p);
    asm volatile("ldmatrix.sync.aligned.m8n8.x4.shared.b16 {%0,%1,%2,%3}, [%4];"
                 : "=r"(r[0]), "=r"(r[1]), "=r"(r[2]), "=r"(r[3]) : "r"(a));
}

__device__ __forceinline__ void mma16816(float* c, const unsigned* a, const unsigned* b)
{
    asm volatile("mma.sync.aligned.m16n8k16.row.col.f32.f16.f16.f32 "
                 "{%0,%1,%2,%3},{%4,%5,%6,%7},{%8,%9},{%0,%1,%2,%3};"
                 : "+f"(c[0]), "+f"(c[1]), "+f"(c[2]), "+f"(c[3])
                 : "r"(a[0]), "r"(a[1]), "r"(a[2]), "r"(a[3]), "r"(b[0]), "r"(b[1]));
}

__device__ __forceinline__ void cp16(void* sdst, const void* gsrc)
{
    unsigned s = (unsigned)__cvta_generic_to_shared(sdst);
    asm volatile("cp.async.cg.shared.global [%0], [%1], 16;" :: "r"(s), "l"(gsrc) : "memory");
}

// ---------------- pipelined fp16 GEMM (validated R11): C = A * W^T + bias ----------------
#define SROW 40
#define STAGE_ELEMS (128 * SROW)
#define STAGE_BYTES (2 * STAGE_ELEMS * 2)
__global__ void __launch_bounds__(256, 2)
gemm_fp16(int a_sel, int set, const float* __restrict__ bias, int c_sel)
{
    extern __shared__ __align__(16) __half smem[];
    float* C = c_sel ? g_Gb : g_Gf;
    const __half* Apl = (a_sel == 0) ? g_Ah : (a_sel == 1) ? g_Ahf : g_Ahb;
    const __half* Wpl = g_Wh[set];

    const int tid    = threadIdx.x;
    const int lane   = tid & 31;
    const int wid    = tid >> 5;
    const int warp_m = wid & 3;
    const int warp_n = wid >> 2;

    const size_t rowA0 = (size_t)blockIdx.y * 128;
    const size_t rowW0 = (size_t)blockIdx.x * 128;

    const int amr = warp_m * 32 + (lane & 15);
    const int akc = (lane >> 4) << 3;
    const int wnr = warp_n * 64 + (lane & 7) + ((lane >> 4) << 3);
    const int wkc = ((lane >> 3) & 1) << 3;

    float acc[2][8][4];
#pragma unroll
    for (int i = 0; i < 2; i++)
#pragma unroll
        for (int j = 0; j < 8; j++)
#pragma unroll
            for (int q = 0; q < 4; q++) acc[i][j][q] = 0.f;

    auto load_stage = [&](int st, int k0) {
        __half* sb = smem + (size_t)st * 2 * STAGE_ELEMS;
#pragma unroll
        for (int i = 0; i < 4; i++) {
            int u = tid + 256 * i;
            int plane = u >> 9;
            int r = (u >> 2) & 127;
            int c = u & 3;
            const __half* src = (plane == 0 ? Apl + (rowA0 + r) * 1024
                                            : Wpl + (rowW0 + r) * 1024) + k0 + c * 8;
            cp16(sb + plane * STAGE_ELEMS + r * SROW + c * 8, src);
        }
        asm volatile("cp.async.commit_group;" ::: "memory");
    };

    load_stage(0, 0);
    load_stage(1, 32);

    for (int cc = 0; cc < 32; cc++) {
        if (cc < 31) { asm volatile("cp.async.wait_group 1;" ::: "memory"); }
        else         { asm volatile("cp.async.wait_group 0;" ::: "memory"); }
        __syncthreads();
        if (cc + 2 < 32) load_stage((cc + 2) % 3, (cc + 2) * 32);

        const __half* sA = smem + (size_t)(cc % 3) * 2 * STAGE_ELEMS;
        const __half* sW = sA + STAGE_ELEMS;

#pragma unroll
        for (int kk = 0; kk < 32; kk += 16) {
            unsigned Af[2][4], Wf[4][4];
#pragma unroll
            for (int mt = 0; mt < 2; mt++)
                ldsm4(Af[mt], sA + (amr + mt * 16) * SROW + akc + kk);
#pragma unroll
            for (int q = 0; q < 4; q++)
                ldsm4(Wf[q], sW + (wnr + q * 16) * SROW + wkc + kk);
#pragma unroll
            for (int mt = 0; mt < 2; mt++)
#pragma unroll
                for (int nt = 0; nt < 8; nt++)
                    mma16816(acc[mt][nt], Af[mt], &Wf[nt >> 1][(nt & 1) * 2]);
        }
        __syncthreads();
    }

    const int rbase = blockIdx.y * 128 + warp_m * 32 + (lane >> 2);
    const int cbase = blockIdx.x * 128 + warp_n * 64 + (lane & 3) * 2;
#pragma unroll
    for (int nt = 0; nt < 8; nt++) {
        int col = cbase + nt * 8;
        float b0 = bias[col], b1 = bias[col + 1];
#pragma unroll
        for (int mt = 0; mt < 2; mt++) {
            int r = rbase + mt * 16;
            *(float2*)(C + (size_t)r * G4 + col) =
                make_float2(acc[mt][nt][0] + b0, acc[mt][nt][1] + b1);
            *(float2*)(C + (size_t)(r + 8) * G4 + col) =
                make_float2(acc[mt][nt][2] + b0, acc[mt][nt][3] + b1);
        }
    }
}

// ---------------- persistent MMA LSTM recurrence ----------------
// 128 CTAs: dir x 16-unit tile (64 gate-cols). Whh slice fp16 resident in smem
// (loaded once). Per step: stream h(t-1) fp16 (3-stage cp.async), 64x64 HMMA,
// fragments -> smem (aliased over h buffers) -> activation epilogue, c in regs.
#define WPAD 1032                   // W smem row halfs (2064B: +16B/row shift)
#define APAD 72                     // h smem row halfs (144B)
#define HBUF (64 * APAD)            // halfs per h stage
#define RSMEM (64 * WPAD * 2 + 3 * HBUF * 2)   // 132096 + 27648 = 159744 B
__global__ void __launch_bounds__(256, 1)
lstm_recur_kernel(const float* __restrict__ Whh_f, const float* __restrict__ Whh_b,
                  int out_sel)
{
    extern __shared__ __align__(16) __half dsm[];
    __half* sW = dsm;
    __half* sH = dsm + 64 * WPAD;
    float*  sAcc = (float*)sH;                 // alias (stride 68) after k-loop

    const int d  = blockIdx.x >> 6;
    const int u0 = (blockIdx.x & 63) * 16;
    const float*  W  = d ? Whh_b : Whh_f;
    const float*  Gd = d ? g_Gb : g_Gf;
    __half*       Hh = out_sel ? (d ? g_B1b : g_B1f) : (d ? g_Ahb : g_Ahf);
    float*        H32 = out_sel ? (d ? g_Hb1 : g_Hf1) : (float*)0;

    const int tid    = threadIdx.x;
    const int lane   = tid & 31;
    const int wid    = tid >> 5;
    const int warp_m = wid & 3;                // m16 tile (batch rows)
    const int warp_n = wid >> 2;               // n32 tile (gate cols)

    // ---- load resident Whh slice -> fp16 smem (once) ----
    {
        int j    = tid >> 2;                   // smem col-row 0..63: col j = uu*4+g
        int kseg = (tid & 3) * 256;
        int grow = (j & 3) * 1024 + u0 + (j >> 2);
        const float4* src = (const float4*)(W + (size_t)grow * 1024 + kseg);
        __half* dst = sW + (size_t)j * WPAD + kseg;
#pragma unroll 8
        for (int i = 0; i < 64; i++) {
            float4 v = src[i];
            __half2 a = __floats2half2_rn(v.x, v.y);
            __half2 b = __floats2half2_rn(v.z, v.w);
            ((uint2*)dst)[i] = make_uint2(*(unsigned*)&a, *(unsigned*)&b);
        }
    }
    __syncthreads();

    const int amr = warp_m * 16 + (lane & 15);
    const int akc = (lane >> 4) << 3;
    const int wnr = warp_n * 32 + (lane & 7) + ((lane >> 4) << 3);
    const int wkc = ((lane >> 3) & 1) << 3;

    // epilogue mapping: thread -> batch pair (b0,b0+1) x 2 units x 4 gates
    const int et  = tid >> 2;
    const int ep  = tid & 3;
    const int b0  = (et & 7) * 8 + ep * 2;
    const int uu0 = (et >> 3) * 2;             // local unit offset

    float cst[2][2] = {{0.f, 0.f}, {0.f, 0.f}};

    for (int ts = 0; ts < SEQ; ts++) {
        const int sidx = d ? (SEQ - 1 - ts) : ts;
        const float* G = Gd + (size_t)sidx * BATCH * G4;

        float gp0[2][4], gp1[2][4];
#pragma unroll
        for (int us = 0; us < 2; us++)
#pragma unroll
            for (int gt = 0; gt < 4; gt++) {
                gp0[us][gt] = G[(size_t)b0 * G4 + gt * 1024 + u0 + uu0 + us];
                gp1[us][gt] = G[(size_t)(b0 + 1) * G4 + gt * 1024 + u0 + uu0 + us];
            }

        float acc[4][4];
#pragma unroll
        for (int i = 0; i < 4; i++)
#pragma unroll
            for (int j = 0; j < 4; j++) acc[i][j] = 0.f;

        if (ts > 0) {
            const __half* hin = Hh + (size_t)(d ? sidx + 1 : sidx - 1) * BATCH * HID;

            auto loadc = [&](int st, int ch) {
                __half* hb = sH + st * HBUF;
#pragma unroll
                for (int i = 0; i < 2; i++) {
                    int q = tid * 2 + i;               // 0..511
                    int r = q >> 3, cs = q & 7;
                    cp16(hb + r * APAD + cs * 8,
                         hin + (size_t)r * HID + ch * 64 + cs * 8);
                }
                asm volatile("cp.async.commit_group;" ::: "memory");
            };

            loadc(0, 0);
            loadc(1, 1);

            for (int ch = 0; ch < 16; ch++) {
                if (ch < 15) { asm volatile("cp.async.wait_group 1;" ::: "memory"); }
                else         { asm volatile("cp.async.wait_group 0;" ::: "memory"); }
                __syncthreads();
                if (ch + 2 < 16) loadc((ch + 2) % 3, ch + 2);

                const __half* hb = sH + (ch % 3) * HBUF;
#pragma unroll
                for (int kk = 0; kk < 64; kk += 16) {
                    unsigned Af[4], Wf[2][4];
                    ldsm4(Af, hb + amr * APAD + akc + kk);
                    int kg = ch * 64 + kk;
#pragma unroll
                    for (int q = 0; q < 2; q++)
                        ldsm4(Wf[q], sW + (size_t)(wnr + q * 16) * WPAD + wkc + kg);
#pragma unroll
                    for (int nt = 0; nt < 4; nt++)
                        mma16816(acc[nt], Af, &Wf[nt >> 1][(nt & 1) * 2]);
                }
                __syncthreads();
            }
        }

        // ---- fragments -> smem (aliases dead h buffers) ----
        {
            const int r0 = warp_m * 16 + (lane >> 2);
            const int c0 = warp_n * 32 + (lane & 3) * 2;
#pragma unroll
            for (int nt = 0; nt < 4; nt++) {
                int c = c0 + nt * 8;
                *(float2*)&sAcc[(size_t)r0 * 68 + c]       = make_float2(acc[nt][0], acc[nt][1]);
                *(float2*)&sAcc[(size_t)(r0 + 8) * 68 + c] = make_float2(acc[nt][2], acc[nt][3]);
            }
        }
        __syncthreads();

        // ---- activations + c update + h writes ----
        __half* hw = Hh + (size_t)sidx * BATCH * HID;
#pragma unroll
        for (int us = 0; us < 2; us++) {
            int uu = uu0 + us;
            float4 ga = *(const float4*)&sAcc[(size_t)b0 * 68 + uu * 4];
            float4 gb = *(const float4*)&sAcc[(size_t)(b0 + 1) * 68 + uu * 4];
            float gi0 = ga.x + gp0[us][0], gi1 = gb.x + gp1[us][0];
            float gf0 = ga.y + gp0[us][1], gf1 = gb.y + gp1[us][1];
            float gg0 = ga.z + gp0[us][2], gg1 = gb.z + gp1[us][2];
            float go0 = ga.w + gp0[us][3], go1 = gb.w + gp1[us][3];
            float iv0 = 1.f / (1.f + expf(-gi0)), iv1 = 1.f / (1.f + expf(-gi1));
            float fv0 = 1.f / (1.f + expf(-gf0)), fv1 = 1.f / (1.f + expf(-gf1));
            float ov0 = 1.f / (1.f + expf(-go0)), ov1 = 1.f / (1.f + expf(-go1));
            float cn0 = fv0 * cst[us][0] + iv0 * tanhf(gg0);
            float cn1 = fv1 * cst[us][1] + iv1 * tanhf(gg1);
            cst[us][0] = cn0;
            cst[us][1] = cn1;
            float h0 = ov0 * tanhf(cn0);
            float h1 = ov1 * tanhf(cn1);
            int u = u0 + uu;
            hw[(size_t)b0 * HID + u]       = __float2half_rn(h0);
            hw[(size_t)(b0 + 1) * HID + u] = __float2half_rn(h1);
            if (out_sel) {
                H32[(size_t)sidx * BATCH * HID + (size_t)b0 * HID + u]       = h0;
                H32[(size_t)sidx * BATCH * HID + (size_t)(b0 + 1) * HID + u] = h1;
            }
        }

        grid_sync();
    }
}

// ---------------- output projection ----------------
__global__ void __launch_bounds__(256)
out_kernel(const float* __restrict__ Wout, const float* __restrict__ bout,
           float* __restrict__ out)
{
    __shared__ __align__(16) float hf[4][HID];
    __shared__ __align__(16) float hb[4][HID];
    const int tid   = threadIdx.x;
    const int pair0 = blockIdx.x * 4;

    for (int i = tid; i < 2048; i += 256) {
        int p   = i >> 9;
        int rem = i & 511;
        int sb  = pair0 + p;
        int r4  = rem & 255;
        const float* src = (rem < 256 ? g_Hf1 : g_Hb1) + (size_t)sb * HID;
        float4 v = ((const float4*)src)[r4];
        if (rem < 256) ((float4*)hf[p])[r4] = v;
        else           ((float4*)hb[p])[r4] = v;
    }
    __syncthreads();

    int p = tid >> 6;
    int o = tid & 63;
    if (o < OUTD) {
        int sb = pair0 + p;
        int s = sb >> 6, b = sb & 63;
        const float4* w0  = (const float4*)(Wout + (size_t)o * 2 * HID);
        const float4* w1  = w0 + 256;
        const float4* hf4 = (const float4*)hf[p];
        const float4* hb4 = (const float4*)hb[p];
        float acc = 0.f;
#pragma unroll 4
        for (int k = 0; k < 256; k++) {
            float4 a = hf4[k]; float4 w = w0[k];
            acc += a.x*w.x + a.y*w.y + a.z*w.z + a.w*w.w;
        }
#pragma unroll 4
        for (int k = 0; k < 256; k++) {
            float4 a = hb4[k]; float4 w = w1[k];
            acc += a.x*w.x + a.y*w.y + a.z*w.z + a.w*w.w;
        }
        out[((size_t)b * SEQ + s) * OUTD + o] = acc + bout[o];
    }
}

// ---------------- launch sequence ----------------
extern "C" void kernel_launch(void* const* d_in, const int* in_sizes, int n_in,
                              void* d_out, int out_size)
{
    const int*   src   = (const int*)  d_in[0];
    const float* emb   = (const float*)d_in[1];
    const float* Wih_f = (const float*)d_in[2];
    const float* Whh_f = (const float*)d_in[3];
    const float* b_f   = (const float*)d_in[4];
    const float* Wih_b = (const float*)d_in[5];
    const float* Whh_b = (const float*)d_in[6];
    const float* b_b   = (const float*)d_in[7];
    const float* Wout  = (const float*)d_in[8];
    const float* bout  = (const float*)d_in[9];
    float* out = (float*)d_out;
    (void)in_sizes; (void)n_in; (void)out_size;

    cudaFuncSetAttribute(gemm_fp16,
                         cudaFuncAttributeMaxDynamicSharedMemorySize, 3 * STAGE_BYTES);
    cudaFuncSetAttribute(lstm_recur_kernel,
                         cudaFuncAttributeMaxDynamicSharedMemorySize, RSMEM);

    embed_kernel<<<SEQ * BATCH * (EMB / 4) / 256, 256>>>(src, emb);

    dim3 ggrid(G4 / 128, (SEQ * BATCH) / 128);                 // (32, 256)
    const int convW_blocks = (G4 * 1024 / 4) / 256;            // 4096

    for (int l = 0; l < 2; l++) {
        size_t woff = (size_t)l * G4 * 1024;
        int a_f = (l == 0) ? 0 : 1;   // X or layer0-fwd h (fp16)
        int a_b = (l == 0) ? 0 : 2;   // X or layer0-bwd h (fp16)
        convW_kernel<<<convW_blocks, 256>>>(Wih_f + woff, 0);
        convW_kernel<<<convW_blocks, 256>>>(Wih_b + woff, 1);
        gemm_fp16<<<ggrid, 256, 3 * STAGE_BYTES>>>(a_f, 0, b_f + l * G4, 0);
        gemm_fp16<<<ggrid, 256, 3 * STAGE_BYTES>>>(a_b, 1, b_b + l * G4, 1);
        lstm_recur_kernel<<<NCTA, 256, RSMEM>>>(Whh_f + woff, Whh_b + woff, l);
    }

    out_kernel<<<(SEQ * BATCH) / 4, 256>>>(Wout, bout, out);
}

// round 13
// speedup vs baseline: 4.7333x; 1.0621x over previous
#include <cuda_runtime.h>
#include <cuda_fp16.h>
#include <math.h>
#include <stdint.h>

#define BATCH 64
#define SEQ   512
#define EMB   1024
#define HID   1024
#define G4    4096
#define OUTD  50
#define NCTA  128   // persistent recurrence grid

// ---------------- static device scratch (no cudaMalloc allowed) ----------------
__device__ float g_Gf [(size_t)SEQ * BATCH * G4];
__device__ float g_Gb [(size_t)SEQ * BATCH * G4];
__device__ float g_Hf1[(size_t)SEQ * BATCH * HID];
__device__ float g_Hb1[(size_t)SEQ * BATCH * HID];
__device__ unsigned g_bar;

// fp16 planes
__device__ __half g_Ah [(size_t)SEQ * BATCH * 1024];
__device__ __half g_Ahf[(size_t)SEQ * BATCH * 1024];
__device__ __half g_Ahb[(size_t)SEQ * BATCH * 1024];
__device__ __half g_B1f[(size_t)SEQ * BATCH * 1024];
__device__ __half g_B1b[(size_t)SEQ * BATCH * 1024];
__device__ __half g_Wh [2][(size_t)G4 * 1024];

// ---------------- software grid barrier ----------------
__device__ __forceinline__ void grid_sync()
{
    __syncthreads();
    if (threadIdx.x == 0) {
        __threadfence();
        unsigned ticket = atomicAdd(&g_bar, 1u);
        unsigned target = (ticket & ~(unsigned)(NCTA - 1)) + NCTA;
        while ((int)(*(volatile unsigned*)&g_bar - target) < 0) { }
        __threadfence();
    }
    __syncthreads();
}

// ---------------- embedding gather: writes fp16 A plane directly ----------------
__global__ void embed_kernel(const int* __restrict__ src, const float* __restrict__ emb)
{
    size_t idx = (size_t)blockIdx.x * blockDim.x + threadIdx.x;
    int    e4  = (int)(idx & (EMB / 4 - 1));
    size_t sb  = idx >> 8;
    int    b   = (int)(sb & (BATCH - 1));
    int    s   = (int)(sb >> 6);
    int    tok = src[b * SEQ + s];
    float4 v = ((const float4*)(emb + (size_t)tok * EMB))[e4];
    __half2 h01 = __floats2half2_rn(v.x, v.y);
    __half2 h23 = __floats2half2_rn(v.z, v.w);
    ((uint2*)g_Ah)[idx] = make_uint2(*(unsigned*)&h01, *(unsigned*)&h23);
}

// ---------------- fp32 -> fp16 W conversion ----------------
__global__ void convW_kernel(const float* __restrict__ W, int set)
{
    size_t i = (size_t)blockIdx.x * blockDim.x + threadIdx.x;
    float4 v = ((const float4*)W)[i];
    __half2 h01 = __floats2half2_rn(v.x, v.y);
    __half2 h23 = __floats2half2_rn(v.z, v.w);
    ((uint2*)g_Wh[set])[i] = make_uint2(*(unsigned*)&h01, *(unsigned*)&h23);
}

// ---------------- tensor-core helpers ----------------
__device__ __forceinline__ void ldsm4(unsigned* r, const __half* p)
{
    unsigned a = (unsigned)__cvta_generic_to_shared(p);
    asm volatile("ldmatrix.sync.aligned.m8n8.x4.shared.b16 {%0,%1,%2,%3}, [%4];"
                 : "=r"(r[0]), "=r"(r[1]), "=r"(r[2]), "=r"(r[3]) : "r"(a));
}

__device__ __forceinline__ void mma16816(float* c, const unsigned* a, const unsigned* b)
{
    asm volatile("mma.sync.aligned.m16n8k16.row.col.f32.f16.f16.f32 "
                 "{%0,%1,%2,%3},{%4,%5,%6,%7},{%8,%9},{%0,%1,%2,%3};"
                 : "+f"(c[0]), "+f"(c[1]), "+f"(c[2]), "+f"(c[3])
                 : "r"(a[0]), "r"(a[1]), "r"(a[2]), "r"(a[3]), "r"(b[0]), "r"(b[1]));
}

__device__ __forceinline__ void cp16(void* sdst, const void* gsrc)
{
    unsigned s = (unsigned)__cvta_generic_to_shared(sdst);
    asm volatile("cp.async.cg.shared.global [%0], [%1], 16;" :: "r"(s), "l"(gsrc) : "memory");
}

// ---------------- pipelined fp16 GEMM (validated R11/R12): C = A * W^T + bias ----------------
#define SROW 40
#define STAGE_ELEMS (128 * SROW)
#define STAGE_BYTES (2 * STAGE_ELEMS * 2)
__global__ void __launch_bounds__(256, 2)
gemm_fp16(int a_sel, int set, const float* __restrict__ bias, int c_sel)
{
    extern __shared__ __align__(16) __half smem[];
    float* C = c_sel ? g_Gb : g_Gf;
    const __half* Apl = (a_sel == 0) ? g_Ah : (a_sel == 1) ? g_Ahf : g_Ahb;
    const __half* Wpl = g_Wh[set];

    const int tid    = threadIdx.x;
    const int lane   = tid & 31;
    const int wid    = tid >> 5;
    const int warp_m = wid & 3;
    const int warp_n = wid >> 2;

    const size_t rowA0 = (size_t)blockIdx.y * 128;
    const size_t rowW0 = (size_t)blockIdx.x * 128;

    const int amr = warp_m * 32 + (lane & 15);
    const int akc = (lane >> 4) << 3;
    const int wnr = warp_n * 64 + (lane & 7) + ((lane >> 4) << 3);
    const int wkc = ((lane >> 3) & 1) << 3;

    float acc[2][8][4];
#pragma unroll
    for (int i = 0; i < 2; i++)
#pragma unroll
        for (int j = 0; j < 8; j++)
#pragma unroll
            for (int q = 0; q < 4; q++) acc[i][j][q] = 0.f;

    auto load_stage = [&](int st, int k0) {
        __half* sb = smem + (size_t)st * 2 * STAGE_ELEMS;
#pragma unroll
        for (int i = 0; i < 4; i++) {
            int u = tid + 256 * i;
            int plane = u >> 9;
            int r = (u >> 2) & 127;
            int c = u & 3;
            const __half* src = (plane == 0 ? Apl + (rowA0 + r) * 1024
                                            : Wpl + (rowW0 + r) * 1024) + k0 + c * 8;
            cp16(sb + plane * STAGE_ELEMS + r * SROW + c * 8, src);
        }
        asm volatile("cp.async.commit_group;" ::: "memory");
    };

    load_stage(0, 0);
    load_stage(1, 32);

    for (int cc = 0; cc < 32; cc++) {
        if (cc < 31) { asm volatile("cp.async.wait_group 1;" ::: "memory"); }
        else         { asm volatile("cp.async.wait_group 0;" ::: "memory"); }
        __syncthreads();
        if (cc + 2 < 32) load_stage((cc + 2) % 3, (cc + 2) * 32);

        const __half* sA = smem + (size_t)(cc % 3) * 2 * STAGE_ELEMS;
        const __half* sW = sA + STAGE_ELEMS;

#pragma unroll
        for (int kk = 0; kk < 32; kk += 16) {
            unsigned Af[2][4], Wf[4][4];
#pragma unroll
            for (int mt = 0; mt < 2; mt++)
                ldsm4(Af[mt], sA + (amr + mt * 16) * SROW + akc + kk);
#pragma unroll
            for (int q = 0; q < 4; q++)
                ldsm4(Wf[q], sW + (wnr + q * 16) * SROW + wkc + kk);
#pragma unroll
            for (int mt = 0; mt < 2; mt++)
#pragma unroll
                for (int nt = 0; nt < 8; nt++)
                    mma16816(acc[mt][nt], Af[mt], &Wf[nt >> 1][(nt & 1) * 2]);
        }
        __syncthreads();
    }

    const int rbase = blockIdx.y * 128 + warp_m * 32 + (lane >> 2);
    const int cbase = blockIdx.x * 128 + warp_n * 64 + (lane & 3) * 2;
#pragma unroll
    for (int nt = 0; nt < 8; nt++) {
        int col = cbase + nt * 8;
        float b0 = bias[col], b1 = bias[col + 1];
#pragma unroll
        for (int mt = 0; mt < 2; mt++) {
            int r = rbase + mt * 16;
            *(float2*)(C + (size_t)r * G4 + col) =
                make_float2(acc[mt][nt][0] + b0, acc[mt][nt][1] + b1);
            *(float2*)(C + (size_t)(r + 8) * G4 + col) =
                make_float2(acc[mt][nt][2] + b0, acc[mt][nt][3] + b1);
        }
    }
}

// ---------------- persistent MMA LSTM recurrence (v2) ----------------
// vs R12: gpre via cp.async into smem (prefetched under the previous step's
// grid barrier), k-chunk 128 (8 chunks), trailing per-chunk sync removed,
// half2/float2 coalesced h writes.
#define WPAD  1032                   // W smem row halfs
#define WHALF (64 * WPAD)            // 66048 halfs
#define APAD  136                    // h smem row halfs (272B, conflict-free ldsm)
#define HBUF  (64 * APAD)            // 8704 halfs per stage
#define SGOFF (WHALF + 3 * HBUF)     // 92160 halfs
#define RSMEM (SGOFF * 2 + 16384)    // 200704 B
__global__ void __launch_bounds__(256, 1)
lstm_recur_kernel(const float* __restrict__ Whh_f, const float* __restrict__ Whh_b,
                  int out_sel)
{
    extern __shared__ __align__(16) __half dsm[];
    __half* sW   = dsm;
    __half* sH   = dsm + WHALF;
    float*  sAcc = (float*)sH;                 // alias (stride 68) after k-loop
    float*  sG   = (float*)(dsm + SGOFF);      // gate pre-activations, 16KB

    const int d  = blockIdx.x >> 6;
    const int u0 = (blockIdx.x & 63) * 16;
    const float*  W  = d ? Whh_b : Whh_f;
    const float*  Gd = d ? g_Gb : g_Gf;
    __half*       Hh = out_sel ? (d ? g_B1b : g_B1f) : (d ? g_Ahb : g_Ahf);
    float*        H32 = out_sel ? (d ? g_Hb1 : g_Hf1) : (float*)0;

    const int tid    = threadIdx.x;
    const int lane   = tid & 31;
    const int wid    = tid >> 5;
    const int warp_m = wid & 3;
    const int warp_n = wid >> 2;

    // ---- load resident Whh slice -> fp16 smem (once) ----
    {
        int j    = tid >> 2;
        int kseg = (tid & 3) * 256;
        int grow = (j & 3) * 1024 + u0 + (j >> 2);
        const float4* src = (const float4*)(W + (size_t)grow * 1024 + kseg);
        __half* dst = sW + (size_t)j * WPAD + kseg;
#pragma unroll 8
        for (int i = 0; i < 64; i++) {
            float4 v = src[i];
            __half2 a = __floats2half2_rn(v.x, v.y);
            __half2 b = __floats2half2_rn(v.z, v.w);
            ((uint2*)dst)[i] = make_uint2(*(unsigned*)&a, *(unsigned*)&b);
        }
    }
    __syncthreads();

    const int amr = warp_m * 16 + (lane & 15);
    const int akc = (lane >> 4) << 3;
    const int wnr = warp_n * 32 + (lane & 7) + ((lane >> 4) << 3);
    const int wkc = ((lane >> 3) & 1) << 3;

    // epilogue mapping: thread -> batch pair (b0,b0+1) x 2 units x 4 gates
    const int et  = tid >> 2;
    const int ep  = tid & 3;
    const int b0  = (et & 7) * 8 + ep * 2;
    const int uu0 = (et >> 3) * 2;

    // gpre loader: 1024 cp16 (64B contiguous per (b,gate) segment)
    auto issue_gpre = [&](const float* G) {
#pragma unroll
        for (int i = 0; i < 4; i++) {
            int seg = tid + 256 * i;
            int b   = seg >> 4;
            int gt  = (seg >> 2) & 3;
            int qq  = seg & 3;
            cp16(sG + ((size_t)(b * 4 + gt) * 16 + qq * 4),
                 G + (size_t)b * G4 + gt * 1024 + u0 + qq * 4);
        }
        asm volatile("cp.async.commit_group;" ::: "memory");
    };

    float cst[2][2] = {{0.f, 0.f}, {0.f, 0.f}};

    // prefetch gpre for step 0
    issue_gpre(Gd + (size_t)(d ? SEQ - 1 : 0) * BATCH * G4);

    for (int ts = 0; ts < SEQ; ts++) {
        const int sidx = d ? (SEQ - 1 - ts) : ts;

        float acc[4][4];
#pragma unroll
        for (int i = 0; i < 4; i++)
#pragma unroll
            for (int j = 0; j < 4; j++) acc[i][j] = 0.f;

        if (ts > 0) {
            const __half* hin = Hh + (size_t)(d ? sidx + 1 : sidx - 1) * BATCH * HID;

            auto loadc = [&](int st, int ch) {
                __half* hb = sH + st * HBUF;
#pragma unroll
                for (int i = 0; i < 4; i++) {
                    int seg = tid + 256 * i;             // 0..1023
                    int r = seg >> 4, cs = seg & 15;
                    cp16(hb + r * APAD + cs * 8,
                         hin + (size_t)r * HID + ch * 128 + cs * 8);
                }
                asm volatile("cp.async.commit_group;" ::: "memory");
            };

            loadc(0, 0);
            loadc(1, 1);

            for (int ch = 0; ch < 8; ch++) {
                if (ch < 7) { asm volatile("cp.async.wait_group 1;" ::: "memory"); }
                else        { asm volatile("cp.async.wait_group 0;" ::: "memory"); }
                __syncthreads();
                if (ch + 2 < 8) loadc((ch + 2) % 3, ch + 2);

                const __half* hb = sH + (ch % 3) * HBUF;
#pragma unroll
                for (int kk = 0; kk < 128; kk += 16) {
                    unsigned Af[4], Wf[2][4];
                    ldsm4(Af, hb + amr * APAD + akc + kk);
                    int kg = ch * 128 + kk;
#pragma unroll
                    for (int q = 0; q < 2; q++)
                        ldsm4(Wf[q], sW + (size_t)(wnr + q * 16) * WPAD + wkc + kg);
#pragma unroll
                    for (int nt = 0; nt < 4; nt++)
                        mma16816(acc[nt], Af, &Wf[nt >> 1][(nt & 1) * 2]);
                }
                // no trailing sync: next iteration's top sync orders stage reuse
            }
        } else {
            asm volatile("cp.async.wait_group 0;" ::: "memory");   // gpre
        }

        // ---- fragments -> smem (aliases stage 0; last-read at ch=6, safe) ----
        {
            const int r0 = warp_m * 16 + (lane >> 2);
            const int c0 = warp_n * 32 + (lane & 3) * 2;
#pragma unroll
            for (int nt = 0; nt < 4; nt++) {
                int c = c0 + nt * 8;
                *(float2*)&sAcc[(size_t)r0 * 68 + c]       = make_float2(acc[nt][0], acc[nt][1]);
                *(float2*)&sAcc[(size_t)(r0 + 8) * 68 + c] = make_float2(acc[nt][2], acc[nt][3]);
            }
        }
        __syncthreads();

        // ---- activations + c update + coalesced h writes ----
        __half* hw = Hh + (size_t)sidx * BATCH * HID;
        float hv0[2], hv1[2];
#pragma unroll
        for (int us = 0; us < 2; us++) {
            int uu = uu0 + us;
            float4 ga = *(const float4*)&sAcc[(size_t)b0 * 68 + uu * 4];
            float4 gb = *(const float4*)&sAcc[(size_t)(b0 + 1) * 68 + uu * 4];
            float gi0 = ga.x + sG[((size_t)b0 * 4 + 0) * 16 + uu];
            float gf0 = ga.y + sG[((size_t)b0 * 4 + 1) * 16 + uu];
            float gg0 = ga.z + sG[((size_t)b0 * 4 + 2) * 16 + uu];
            float go0 = ga.w + sG[((size_t)b0 * 4 + 3) * 16 + uu];
            float gi1 = gb.x + sG[((size_t)(b0 + 1) * 4 + 0) * 16 + uu];
            float gf1 = gb.y + sG[((size_t)(b0 + 1) * 4 + 1) * 16 + uu];
            float gg1 = gb.z + sG[((size_t)(b0 + 1) * 4 + 2) * 16 + uu];
            float go1 = gb.w + sG[((size_t)(b0 + 1) * 4 + 3) * 16 + uu];
            float iv0 = 1.f / (1.f + expf(-gi0)), iv1 = 1.f / (1.f + expf(-gi1));
            float fv0 = 1.f / (1.f + expf(-gf0)), fv1 = 1.f / (1.f + expf(-gf1));
            float ov0 = 1.f / (1.f + expf(-go0)), ov1 = 1.f / (1.f + expf(-go1));
            float cn0 = fv0 * cst[us][0] + iv0 * tanhf(gg0);
            float cn1 = fv1 * cst[us][1] + iv1 * tanhf(gg1);
            cst[us][0] = cn0;
            cst[us][1] = cn1;
            hv0[us] = ov0 * tanhf(cn0);
            hv1[us] = ov1 * tanhf(cn1);
        }
        {
            int u = u0 + uu0;
            *(__half2*)&hw[(size_t)b0 * HID + u]       = __floats2half2_rn(hv0[0], hv0[1]);
            *(__half2*)&hw[(size_t)(b0 + 1) * HID + u] = __floats2half2_rn(hv1[0], hv1[1]);
            if (out_sel) {
                float* h32r = H32 + (size_t)sidx * BATCH * HID;
                *(float2*)&h32r[(size_t)b0 * HID + u]       = make_float2(hv0[0], hv0[1]);
                *(float2*)&h32r[(size_t)(b0 + 1) * HID + u] = make_float2(hv1[0], hv1[1]);
            }
        }

        // prefetch next step's gpre while waiting at the barrier
        if (ts + 1 < SEQ) {
            __syncthreads();   // all sG reads done before overwrite
            issue_gpre(Gd + (size_t)(d ? SEQ - 2 - ts : ts + 1) * BATCH * G4);
        }

        grid_sync();
    }
}

// ---------------- output projection ----------------
__global__ void __launch_bounds__(256)
out_kernel(const float* __restrict__ Wout, const float* __restrict__ bout,
           float* __restrict__ out)
{
    __shared__ __align__(16) float hf[4][HID];
    __shared__ __align__(16) float hb[4][HID];
    const int tid   = threadIdx.x;
    const int pair0 = blockIdx.x * 4;

    for (int i = tid; i < 2048; i += 256) {
        int p   = i >> 9;
        int rem = i & 511;
        int sb  = pair0 + p;
        int r4  = rem & 255;
        const float* src = (rem < 256 ? g_Hf1 : g_Hb1) + (size_t)sb * HID;
        float4 v = ((const float4*)src)[r4];
        if (rem < 256) ((float4*)hf[p])[r4] = v;
        else           ((float4*)hb[p])[r4] = v;
    }
    __syncthreads();

    int p = tid >> 6;
    int o = tid & 63;
    if (o < OUTD) {
        int sb = pair0 + p;
        int s = sb >> 6, b = sb & 63;
        const float4* w0  = (const float4*)(Wout + (size_t)o * 2 * HID);
        const float4* w1  = w0 + 256;
        const float4* hf4 = (const float4*)hf[p];
        const float4* hb4 = (const float4*)hb[p];
        float acc = 0.f;
#pragma unroll 4
        for (int k = 0; k < 256; k++) {
            float4 a = hf4[k]; float4 w = w0[k];
            acc += a.x*w.x + a.y*w.y + a.z*w.z + a.w*w.w;
        }
#pragma unroll 4
        for (int k = 0; k < 256; k++) {
            float4 a = hb4[k]; float4 w = w1[k];
            acc += a.x*w.x + a.y*w.y + a.z*w.z + a.w*w.w;
        }
        out[((size_t)b * SEQ + s) * OUTD + o] = acc + bout[o];
    }
}

// ---------------- launch sequence ----------------
extern "C" void kernel_launch(void* const* d_in, const int* in_sizes, int n_in,
                              void* d_out, int out_size)
{
    const int*   src   = (const int*)  d_in[0];
    const float* emb   = (const float*)d_in[1];
    const float* Wih_f = (const float*)d_in[2];
    const float* Whh_f = (const float*)d_in[3];
    const float* b_f   = (const float*)d_in[4];
    const float* Wih_b = (const float*)d_in[5];
    const float* Whh_b = (const float*)d_in[6];
    const float* b_b   = (const float*)d_in[7];
    const float* Wout  = (const float*)d_in[8];
    const float* bout  = (const float*)d_in[9];
    float* out = (float*)d_out;
    (void)in_sizes; (void)n_in; (void)out_size;

    cudaFuncSetAttribute(gemm_fp16,
                         cudaFuncAttributeMaxDynamicSharedMemorySize, 3 * STAGE_BYTES);
    cudaFuncSetAttribute(lstm_recur_kernel,
                         cudaFuncAttributeMaxDynamicSharedMemorySize, RSMEM);

    embed_kernel<<<SEQ * BATCH * (EMB / 4) / 256, 256>>>(src, emb);

    dim3 ggrid(G4 / 128, (SEQ * BATCH) / 128);                 // (32, 256)
    const int convW_blocks = (G4 * 1024 / 4) / 256;            // 4096

    for (int l = 0; l < 2; l++) {
        size_t woff = (size_t)l * G4 * 1024;
        int a_f = (l == 0) ? 0 : 1;
        int a_b = (l == 0) ? 0 : 2;
        convW_kernel<<<convW_blocks, 256>>>(Wih_f + woff, 0);
        convW_kernel<<<convW_blocks, 256>>>(Wih_b + woff, 1);
        gemm_fp16<<<ggrid, 256, 3 * STAGE_BYTES>>>(a_f, 0, b_f + l * G4, 0);
        gemm_fp16<<<ggrid, 256, 3 * STAGE_BYTES>>>(a_b, 1, b_b + l * G4, 1);
        lstm_recur_kernel<<<NCTA, 256, RSMEM>>>(Whh_f + woff, Whh_b + woff, l);
    }

    out_kernel<<<(SEQ * BATCH) / 4, 256>>>(Wout, bout, out);
}

// round 14
// speedup vs baseline: 4.9279x; 1.0411x over previous
#include <cuda_runtime.h>
#include <cuda_fp16.h>
#include <math.h>
#include <stdint.h>

#define BATCH 64
#define SEQ   512
#define EMB   1024
#define HID   1024
#define G4    4096
#define OUTD  50
#define NCTA  128   // persistent recurrence grid
#define NCTAD 64    // CTAs per direction (independent barriers)

// ---------------- static device scratch (no cudaMalloc allowed) ----------------
__device__ float g_Gf [(size_t)SEQ * BATCH * G4];
__device__ float g_Gb [(size_t)SEQ * BATCH * G4];
__device__ float g_Hf1[(size_t)SEQ * BATCH * HID];
__device__ float g_Hb1[(size_t)SEQ * BATCH * HID];
__device__ unsigned g_bar2[2][32];   // per-direction barrier counters (line-padded)

// fp16 planes
__device__ __half g_Ah [(size_t)SEQ * BATCH * 1024];
__device__ __half g_Ahf[(size_t)SEQ * BATCH * 1024];
__device__ __half g_Ahb[(size_t)SEQ * BATCH * 1024];
__device__ __half g_B1f[(size_t)SEQ * BATCH * 1024];
__device__ __half g_B1b[(size_t)SEQ * BATCH * 1024];
__device__ __half g_Wh [2][(size_t)G4 * 1024];

// ---------------- per-direction software grid barrier (64 CTAs) ----------------
__device__ __forceinline__ void grid_sync_d(int d)
{
    __syncthreads();
    if (threadIdx.x == 0) {
        __threadfence();
        unsigned ticket = atomicAdd(&g_bar2[d][0], 1u);
        unsigned target = (ticket & ~(unsigned)(NCTAD - 1)) + NCTAD;
        while ((int)(*(volatile unsigned*)&g_bar2[d][0] - target) < 0) { }
        __threadfence();
    }
    __syncthreads();
}

// ---------------- embedding gather: writes fp16 A plane directly ----------------
__global__ void embed_kernel(const int* __restrict__ src, const float* __restrict__ emb)
{
    size_t idx = (size_t)blockIdx.x * blockDim.x + threadIdx.x;
    int    e4  = (int)(idx & (EMB / 4 - 1));
    size_t sb  = idx >> 8;
    int    b   = (int)(sb & (BATCH - 1));
    int    s   = (int)(sb >> 6);
    int    tok = src[b * SEQ + s];
    float4 v = ((const float4*)(emb + (size_t)tok * EMB))[e4];
    __half2 h01 = __floats2half2_rn(v.x, v.y);
    __half2 h23 = __floats2half2_rn(v.z, v.w);
    ((uint2*)g_Ah)[idx] = make_uint2(*(unsigned*)&h01, *(unsigned*)&h23);
}

// ---------------- fp32 -> fp16 W conversion ----------------
__global__ void convW_kernel(const float* __restrict__ W, int set)
{
    size_t i = (size_t)blockIdx.x * blockDim.x + threadIdx.x;
    float4 v = ((const float4*)W)[i];
    __half2 h01 = __floats2half2_rn(v.x, v.y);
    __half2 h23 = __floats2half2_rn(v.z, v.w);
    ((uint2*)g_Wh[set])[i] = make_uint2(*(unsigned*)&h01, *(unsigned*)&h23);
}

// ---------------- tensor-core helpers ----------------
__device__ __forceinline__ void ldsm4(unsigned* r, const __half* p)
{
    unsigned a = (unsigned)__cvta_generic_to_shared(p);
    asm volatile("ldmatrix.sync.aligned.m8n8.x4.shared.b16 {%0,%1,%2,%3}, [%4];"
                 : "=r"(r[0]), "=r"(r[1]), "=r"(r[2]), "=r"(r[3]) : "r"(a));
}

__device__ __forceinline__ void mma16816(float* c, const unsigned* a, const unsigned* b)
{
    asm volatile("mma.sync.aligned.m16n8k16.row.col.f32.f16.f16.f32 "
                 "{%0,%1,%2,%3},{%4,%5,%6,%7},{%8,%9},{%0,%1,%2,%3};"
                 : "+f"(c[0]), "+f"(c[1]), "+f"(c[2]), "+f"(c[3])
                 : "r"(a[0]), "r"(a[1]), "r"(a[2]), "r"(a[3]), "r"(b[0]), "r"(b[1]));
}

__device__ __forceinline__ void cp16(void* sdst, const void* gsrc)
{
    unsigned s = (unsigned)__cvta_generic_to_shared(sdst);
    asm volatile("cp.async.cg.shared.global [%0], [%1], 16;" :: "r"(s), "l"(gsrc) : "memory");
}

// ---------------- pipelined fp16 GEMM (validated R11-R13): C = A * W^T + bias ----------------
#define SROW 40
#define STAGE_ELEMS (128 * SROW)
#define STAGE_BYTES (2 * STAGE_ELEMS * 2)
__global__ void __launch_bounds__(256, 2)
gemm_fp16(int a_sel, int set, const float* __restrict__ bias, int c_sel)
{
    extern __shared__ __align__(16) __half smem[];
    float* C = c_sel ? g_Gb : g_Gf;
    const __half* Apl = (a_sel == 0) ? g_Ah : (a_sel == 1) ? g_Ahf : g_Ahb;
    const __half* Wpl = g_Wh[set];

    const int tid    = threadIdx.x;
    const int lane   = tid & 31;
    const int wid    = tid >> 5;
    const int warp_m = wid & 3;
    const int warp_n = wid >> 2;

    const size_t rowA0 = (size_t)blockIdx.y * 128;
    const size_t rowW0 = (size_t)blockIdx.x * 128;

    const int amr = warp_m * 32 + (lane & 15);
    const int akc = (lane >> 4) << 3;
    const int wnr = warp_n * 64 + (lane & 7) + ((lane >> 4) << 3);
    const int wkc = ((lane >> 3) & 1) << 3;

    float acc[2][8][4];
#pragma unroll
    for (int i = 0; i < 2; i++)
#pragma unroll
        for (int j = 0; j < 8; j++)
#pragma unroll
            for (int q = 0; q < 4; q++) acc[i][j][q] = 0.f;

    auto load_stage = [&](int st, int k0) {
        __half* sb = smem + (size_t)st * 2 * STAGE_ELEMS;
#pragma unroll
        for (int i = 0; i < 4; i++) {
            int u = tid + 256 * i;
            int plane = u >> 9;
            int r = (u >> 2) & 127;
            int c = u & 3;
            const __half* src = (plane == 0 ? Apl + (rowA0 + r) * 1024
                                            : Wpl + (rowW0 + r) * 1024) + k0 + c * 8;
            cp16(sb + plane * STAGE_ELEMS + r * SROW + c * 8, src);
        }
        asm volatile("cp.async.commit_group;" ::: "memory");
    };

    load_stage(0, 0);
    load_stage(1, 32);

    for (int cc = 0; cc < 32; cc++) {
        if (cc < 31) { asm volatile("cp.async.wait_group 1;" ::: "memory"); }
        else         { asm volatile("cp.async.wait_group 0;" ::: "memory"); }
        __syncthreads();
        if (cc + 2 < 32) load_stage((cc + 2) % 3, (cc + 2) * 32);

        const __half* sA = smem + (size_t)(cc % 3) * 2 * STAGE_ELEMS;
        const __half* sW = sA + STAGE_ELEMS;

#pragma unroll
        for (int kk = 0; kk < 32; kk += 16) {
            unsigned Af[2][4], Wf[4][4];
#pragma unroll
            for (int mt = 0; mt < 2; mt++)
                ldsm4(Af[mt], sA + (amr + mt * 16) * SROW + akc + kk);
#pragma unroll
            for (int q = 0; q < 4; q++)
                ldsm4(Wf[q], sW + (wnr + q * 16) * SROW + wkc + kk);
#pragma unroll
            for (int mt = 0; mt < 2; mt++)
#pragma unroll
                for (int nt = 0; nt < 8; nt++)
                    mma16816(acc[mt][nt], Af[mt], &Wf[nt >> 1][(nt & 1) * 2]);
        }
        __syncthreads();
    }

    const int rbase = blockIdx.y * 128 + warp_m * 32 + (lane >> 2);
    const int cbase = blockIdx.x * 128 + warp_n * 64 + (lane & 3) * 2;
#pragma unroll
    for (int nt = 0; nt < 8; nt++) {
        int col = cbase + nt * 8;
        float b0 = bias[col], b1 = bias[col + 1];
#pragma unroll
        for (int mt = 0; mt < 2; mt++) {
            int r = rbase + mt * 16;
            *(float2*)(C + (size_t)r * G4 + col) =
                make_float2(acc[mt][nt][0] + b0, acc[mt][nt][1] + b1);
            *(float2*)(C + (size_t)(r + 8) * G4 + col) =
                make_float2(acc[mt][nt][2] + b0, acc[mt][nt][3] + b1);
        }
    }
}

// ---------------- persistent MMA LSTM recurrence (v3) ----------------
// vs R13: warp tile m32xn32 with 2-way k-split (8 indep acc chains/warp,
// 16 HMMA in flight per SMSP), dual sAcc regions summed in epilogue,
// per-direction grid barrier.
#define WPAD  1032                   // W smem row halfs
#define WHALF (64 * WPAD)            // 66048 halfs
#define APAD  136                    // h smem row halfs (272B, conflict-free ldsm)
#define HBUF  (64 * APAD)            // 8704 halfs per stage
#define SGOFF (WHALF + 3 * HBUF)     // 92160 halfs
#define RSMEM (SGOFF * 2 + 16384)    // 200704 B
__global__ void __launch_bounds__(256, 1)
lstm_recur_kernel(const float* __restrict__ Whh_f, const float* __restrict__ Whh_b,
                  int out_sel)
{
    extern __shared__ __align__(16) __half dsm[];
    __half* sW   = dsm;
    __half* sH   = dsm + WHALF;
    float*  sAcc = (float*)sH;                 // alias: 2 regions of [64][68] fp32
    float*  sG   = (float*)(dsm + SGOFF);      // gate pre-activations, 16KB

    const int d  = blockIdx.x >> 6;
    const int u0 = (blockIdx.x & 63) * 16;
    const float*  W  = d ? Whh_b : Whh_f;
    const float*  Gd = d ? g_Gb : g_Gf;
    __half*       Hh = out_sel ? (d ? g_B1b : g_B1f) : (d ? g_Ahb : g_Ahf);
    float*        H32 = out_sel ? (d ? g_Hb1 : g_Hf1) : (float*)0;

    const int tid  = threadIdx.x;
    const int lane = tid & 31;
    const int wid  = tid >> 5;
    const int wm   = wid & 1;                  // m32 tile
    const int wn   = (wid >> 1) & 1;           // n32 tile
    const int kh   = wid >> 2;                 // k-half

    // ---- load resident Whh slice -> fp16 smem (once) ----
    {
        int j    = tid >> 2;
        int kseg = (tid & 3) * 256;
        int grow = (j & 3) * 1024 + u0 + (j >> 2);
        const float4* src = (const float4*)(W + (size_t)grow * 1024 + kseg);
        __half* dst = sW + (size_t)j * WPAD + kseg;
#pragma unroll 8
        for (int i = 0; i < 64; i++) {
            float4 v = src[i];
            __half2 a = __floats2half2_rn(v.x, v.y);
            __half2 b = __floats2half2_rn(v.z, v.w);
            ((uint2*)dst)[i] = make_uint2(*(unsigned*)&a, *(unsigned*)&b);
        }
    }
    __syncthreads();

    const int amr = wm * 32 + (lane & 15);
    const int akc = ((lane >> 4) << 3) + kh * 64;
    const int wnr = wn * 32 + (lane & 7) + ((lane >> 4) << 3);
    const int wkc = (((lane >> 3) & 1) << 3) + kh * 64;

    // epilogue mapping: thread -> batch pair (b0,b0+1) x 2 units x 4 gates
    const int et  = tid >> 2;
    const int ep  = tid & 3;
    const int b0  = (et & 7) * 8 + ep * 2;
    const int uu0 = (et >> 3) * 2;

    // gpre loader: 1024 cp16 (64B contiguous per (b,gate) segment)
    auto issue_gpre = [&](const float* G) {
#pragma unroll
        for (int i = 0; i < 4; i++) {
            int seg = tid + 256 * i;
            int b   = seg >> 4;
            int gt  = (seg >> 2) & 3;
            int qq  = seg & 3;
            cp16(sG + ((size_t)(b * 4 + gt) * 16 + qq * 4),
                 G + (size_t)b * G4 + gt * 1024 + u0 + qq * 4);
        }
        asm volatile("cp.async.commit_group;" ::: "memory");
    };

    float cst[2][2] = {{0.f, 0.f}, {0.f, 0.f}};

    // prefetch gpre for step 0
    issue_gpre(Gd + (size_t)(d ? SEQ - 1 : 0) * BATCH * G4);

    for (int ts = 0; ts < SEQ; ts++) {
        const int sidx = d ? (SEQ - 1 - ts) : ts;

        float acc[2][4][4];
#pragma unroll
        for (int mt = 0; mt < 2; mt++)
#pragma unroll
            for (int nt = 0; nt < 4; nt++)
#pragma unroll
                for (int q = 0; q < 4; q++) acc[mt][nt][q] = 0.f;

        if (ts > 0) {
            const __half* hin = Hh + (size_t)(d ? sidx + 1 : sidx - 1) * BATCH * HID;

            auto loadc = [&](int st, int ch) {
                __half* hb = sH + st * HBUF;
#pragma unroll
                for (int i = 0; i < 4; i++) {
                    int seg = tid + 256 * i;             // 0..1023
                    int r = seg >> 4, cs = seg & 15;
                    cp16(hb + r * APAD + cs * 8,
                         hin + (size_t)r * HID + ch * 128 + cs * 8);
                }
                asm volatile("cp.async.commit_group;" ::: "memory");
            };

            loadc(0, 0);
            loadc(1, 1);

            for (int ch = 0; ch < 8; ch++) {
                if (ch < 7) { asm volatile("cp.async.wait_group 1;" ::: "memory"); }
                else        { asm volatile("cp.async.wait_group 0;" ::: "memory"); }
                __syncthreads();
                if (ch + 2 < 8) loadc((ch + 2) % 3, ch + 2);

                const __half* hb = sH + (ch % 3) * HBUF;
#pragma unroll
                for (int kk = 0; kk < 64; kk += 16) {
                    unsigned Af[2][4], Wf[2][4];
#pragma unroll
                    for (int mt = 0; mt < 2; mt++)
                        ldsm4(Af[mt], hb + (amr + mt * 16) * APAD + akc + kk);
                    int kg = ch * 128 + wkc + kk;
#pragma unroll
                    for (int q = 0; q < 2; q++)
                        ldsm4(Wf[q], sW + (size_t)(wnr + q * 16) * WPAD + kg);
#pragma unroll
                    for (int mt = 0; mt < 2; mt++)
#pragma unroll
                        for (int nt = 0; nt < 4; nt++)
                            mma16816(acc[mt][nt], Af[mt], &Wf[nt >> 1][(nt & 1) * 2]);
                }
                // no trailing sync: next iteration's top sync orders stage reuse
            }
        } else {
            asm volatile("cp.async.wait_group 0;" ::: "memory");   // gpre
        }

        // ---- fragments -> smem: k-half kh writes its own [64][68] region ----
        {
            float* sAk = sAcc + (size_t)kh * 64 * 68;
            const int c0 = wn * 32 + (lane & 3) * 2;
#pragma unroll
            for (int mt = 0; mt < 2; mt++) {
                int r0 = wm * 32 + mt * 16 + (lane >> 2);
#pragma unroll
                for (int nt = 0; nt < 4; nt++) {
                    int c = c0 + nt * 8;
                    *(float2*)&sAk[(size_t)r0 * 68 + c] =
                        make_float2(acc[mt][nt][0], acc[mt][nt][1]);
                    *(float2*)&sAk[(size_t)(r0 + 8) * 68 + c] =
                        make_float2(acc[mt][nt][2], acc[mt][nt][3]);
                }
            }
        }
        __syncthreads();

        // ---- activations + c update + coalesced h writes ----
        __half* hw = Hh + (size_t)sidx * BATCH * HID;
        float hv0[2], hv1[2];
#pragma unroll
        for (int us = 0; us < 2; us++) {
            int uu = uu0 + us;
            float4 ga0 = *(const float4*)&sAcc[(size_t)b0 * 68 + uu * 4];
            float4 ga1 = *(const float4*)&sAcc[(size_t)(64 * 68) + (size_t)b0 * 68 + uu * 4];
            float4 gb0 = *(const float4*)&sAcc[(size_t)(b0 + 1) * 68 + uu * 4];
            float4 gb1 = *(const float4*)&sAcc[(size_t)(64 * 68) + (size_t)(b0 + 1) * 68 + uu * 4];
            float gi0 = ga0.x + ga1.x + sG[((size_t)b0 * 4 + 0) * 16 + uu];
            float gf0 = ga0.y + ga1.y + sG[((size_t)b0 * 4 + 1) * 16 + uu];
            float gg0 = ga0.z + ga1.z + sG[((size_t)b0 * 4 + 2) * 16 + uu];
            float go0 = ga0.w + ga1.w + sG[((size_t)b0 * 4 + 3) * 16 + uu];
            float gi1 = gb0.x + gb1.x + sG[((size_t)(b0 + 1) * 4 + 0) * 16 + uu];
            float gf1 = gb0.y + gb1.y + sG[((size_t)(b0 + 1) * 4 + 1) * 16 + uu];
            float gg1 = gb0.z + gb1.z + sG[((size_t)(b0 + 1) * 4 + 2) * 16 + uu];
            float go1 = gb0.w + gb1.w + sG[((size_t)(b0 + 1) * 4 + 3) * 16 + uu];
            float iv0 = 1.f / (1.f + expf(-gi0)), iv1 = 1.f / (1.f + expf(-gi1));
            float fv0 = 1.f / (1.f + expf(-gf0)), fv1 = 1.f / (1.f + expf(-gf1));
            float ov0 = 1.f / (1.f + expf(-go0)), ov1 = 1.f / (1.f + expf(-go1));
            float cn0 = fv0 * cst[us][0] + iv0 * tanhf(gg0);
            float cn1 = fv1 * cst[us][1] + iv1 * tanhf(gg1);
            cst[us][0] = cn0;
            cst[us][1] = cn1;
            hv0[us] = ov0 * tanhf(cn0);
            hv1[us] = ov1 * tanhf(cn1);
        }
        {
            int u = u0 + uu0;
            *(__half2*)&hw[(size_t)b0 * HID + u]       = __floats2half2_rn(hv0[0], hv0[1]);
            *(__half2*)&hw[(size_t)(b0 + 1) * HID + u] = __floats2half2_rn(hv1[0], hv1[1]);
            if (out_sel) {
                float* h32r = H32 + (size_t)sidx * BATCH * HID;
                *(float2*)&h32r[(size_t)b0 * HID + u]       = make_float2(hv0[0], hv0[1]);
                *(float2*)&h32r[(size_t)(b0 + 1) * HID + u] = make_float2(hv1[0], hv1[1]);
            }
        }

        // prefetch next step's gpre while waiting at the barrier
        if (ts + 1 < SEQ) {
            __syncthreads();   // all sG/sAcc reads done before overwrite
            issue_gpre(Gd + (size_t)(d ? SEQ - 2 - ts : ts + 1) * BATCH * G4);
        }

        grid_sync_d(d);
    }
}

// ---------------- output projection ----------------
__global__ void __launch_bounds__(256)
out_kernel(const float* __restrict__ Wout, const float* __restrict__ bout,
           float* __restrict__ out)
{
    __shared__ __align__(16) float hf[4][HID];
    __shared__ __align__(16) float hb[4][HID];
    const int tid   = threadIdx.x;
    const int pair0 = blockIdx.x * 4;

    for (int i = tid; i < 2048; i += 256) {
        int p   = i >> 9;
        int rem = i & 511;
        int sb  = pair0 + p;
        int r4  = rem & 255;
        const float* src = (rem < 256 ? g_Hf1 : g_Hb1) + (size_t)sb * HID;
        float4 v = ((const float4*)src)[r4];
        if (rem < 256) ((float4*)hf[p])[r4] = v;
        else           ((float4*)hb[p])[r4] = v;
    }
    __syncthreads();

    int p = tid >> 6;
    int o = tid & 63;
    if (o < OUTD) {
        int sb = pair0 + p;
        int s = sb >> 6, b = sb & 63;
        const float4* w0  = (const float4*)(Wout + (size_t)o * 2 * HID);
        const float4* w1  = w0 + 256;
        const float4* hf4 = (const float4*)hf[p];
        const float4* hb4 = (const float4*)hb[p];
        float acc = 0.f;
#pragma unroll 4
        for (int k = 0; k < 256; k++) {
            float4 a = hf4[k]; float4 w = w0[k];
            acc += a.x*w.x + a.y*w.y + a.z*w.z + a.w*w.w;
        }
#pragma unroll 4
        for (int k = 0; k < 256; k++) {
            float4 a = hb4[k]; float4 w = w1[k];
            acc += a.x*w.x + a.y*w.y + a.z*w.z + a.w*w.w;
        }
        out[((size_t)b * SEQ + s) * OUTD + o] = acc + bout[o];
    }
}

// ---------------- launch sequence ----------------
extern "C" void kernel_launch(void* const* d_in, const int* in_sizes, int n_in,
                              void* d_out, int out_size)
{
    const int*   src   = (const int*)  d_in[0];
    const float* emb   = (const float*)d_in[1];
    const float* Wih_f = (const float*)d_in[2];
    const float* Whh_f = (const float*)d_in[3];
    const float* b_f   = (const float*)d_in[4];
    const float* Wih_b = (const float*)d_in[5];
    const float* Whh_b = (const float*)d_in[6];
    const float* b_b   = (const float*)d_in[7];
    const float* Wout  = (const float*)d_in[8];
    const float* bout  = (const float*)d_in[9];
    float* out = (float*)d_out;
    (void)in_sizes; (void)n_in; (void)out_size;

    cudaFuncSetAttribute(gemm_fp16,
                         cudaFuncAttributeMaxDynamicSharedMemorySize, 3 * STAGE_BYTES);
    cudaFuncSetAttribute(lstm_recur_kernel,
                         cudaFuncAttributeMaxDynamicSharedMemorySize, RSMEM);

    embed_kernel<<<SEQ * BATCH * (EMB / 4) / 256, 256>>>(src, emb);

    dim3 ggrid(G4 / 128, (SEQ * BATCH) / 128);                 // (32, 256)
    const int convW_blocks = (G4 * 1024 / 4) / 256;            // 4096

    for (int l = 0; l < 2; l++) {
        size_t woff = (size_t)l * G4 * 1024;
        int a_f = (l == 0) ? 0 : 1;
        int a_b = (l == 0) ? 0 : 2;
        convW_kernel<<<convW_blocks, 256>>>(Wih_f + woff, 0);
        convW_kernel<<<convW_blocks, 256>>>(Wih_b + woff, 1);
        gemm_fp16<<<ggrid, 256, 3 * STAGE_BYTES>>>(a_f, 0, b_f + l * G4, 0);
        gemm_fp16<<<ggrid, 256, 3 * STAGE_BYTES>>>(a_b, 1, b_b + l * G4, 1);
        lstm_recur_kernel<<<NCTA, 256, RSMEM>>>(Whh_f + woff, Whh_b + woff, l);
    }

    out_kernel<<<(SEQ * BATCH) / 4, 256>>>(Wout, bout, out);
}